// round 10
// baseline (speedup 1.0000x reference)
#include <cuda_runtime.h>
#include <cuda_bf16.h>
#include <cstdint>

#define IMG_N_ANC   8649      // 31*31*9
#define PRE_NMS     6000
#define POST_NMS    1500
#define IOU_THR     0.7f
#define BATCH       16
#define NW          94        // 94 u64 words cover 6016 >= 6000 cols
#define NWP         96        // padded row stride (768 B)
#define NPAD        6016
#define NBIN        2048
#define NKEY        8704      // padded key capacity (>= 8649)
#define NGRP        4         // batch groups for B/C overlap
#define GRP         (BATCH / NGRP)

typedef unsigned long long u64;

// ---------------- device scratch (static; no allocations) ----------------
__device__ u64   g_masks[BATCH][NPAD][NWP];   // [b][row][word], ~73.9 MB
__device__ float g_y1[BATCH][NPAD];
__device__ float g_x1[BATCH][NPAD];
__device__ float g_y2[BATCH][NPAD];
__device__ float g_x2[BATCH][NPAD];
__device__ float g_ar[BATCH][NPAD];
__device__ float g_cs[BATCH][NPAD];           // ar * (0.7/1.7)
__device__ float g_sc[BATCH][NPAD];

// ================= Kernel A: bucket sort + decode top-6000 =================
#define A_NT          1024
#define A_OFF_RAW     0
#define A_OFF_SORT    (NKEY * 8)
#define A_OFF_HIST    (A_OFF_SORT + NKEY * 8)
#define A_OFF_START   (A_OFF_HIST + NBIN * 4)
#define A_SMEM_TOTAL  (A_OFF_START + NBIN * 4)

__global__ __launch_bounds__(A_NT, 1)
void sort_decode_kernel(const float* __restrict__ deltas,
                        const float* __restrict__ probs,
                        const float* __restrict__ anchors)
{
    extern __shared__ char smem[];
    u64* keys_raw    = (u64*)(smem + A_OFF_RAW);
    u64* keys_sorted = (u64*)(smem + A_OFF_SORT);
    unsigned int* hist  = (unsigned int*)(smem + A_OFF_HIST);
    unsigned int* start = (unsigned int*)(smem + A_OFF_START);

    const int b   = blockIdx.x;
    const int tid = threadIdx.x;
    const int nt  = A_NT;

    for (int i = tid; i < NBIN; i += nt) hist[i] = 0u;
    __syncthreads();

    const float* pb = probs + (size_t)b * IMG_N_ANC;
    for (int i = tid; i < IMG_N_ANC; i += nt) {
        float s = pb[i];
        unsigned int bits = __float_as_uint(s);
        u64 k = ((u64)bits << 32) | (u64)(0xFFFFFFFFu - (unsigned)i);
        keys_raw[i] = k;
        int bin = (int)(s * (float)NBIN);
        bin = max(0, min(NBIN - 1, bin));
        atomicAdd(&hist[bin], 1u);
    }
    __syncthreads();

    if (tid < 32) {
        const int lane = tid;
        int part = 0;
        #pragma unroll 8
        for (int q = 0; q < 64; q++) part += (int)hist[NBIN - 1 - (lane * 64 + q)];
        int inc = part;
        #pragma unroll
        for (int off = 1; off < 32; off <<= 1) {
            int v = __shfl_up_sync(0xFFFFFFFFu, inc, off);
            if (lane >= off) inc += v;
        }
        int excl = inc - part;
        for (int q = 0; q < 64; q++) {
            int v = NBIN - 1 - (lane * 64 + q);
            start[v] = (unsigned int)excl;
            excl += (int)hist[v];
        }
    }
    __syncthreads();

    for (int i = tid; i < NBIN; i += nt) hist[i] = 0u;
    __syncthreads();

    for (int i = tid; i < IMG_N_ANC; i += nt) {
        u64 k = keys_raw[i];
        float s = __uint_as_float((unsigned int)(k >> 32));
        int bin = (int)(s * (float)NBIN);
        bin = max(0, min(NBIN - 1, bin));
        unsigned int pos = start[bin] + atomicAdd(&hist[bin], 1u);
        keys_sorted[pos] = k;
    }
    __syncthreads();

    for (int v = tid; v < NBIN; v += nt) {
        int s0 = (int)start[v];
        int c  = (int)hist[v];
        if (s0 < PRE_NMS && c > 1) {
            for (int a = s0 + 1; a < s0 + c; a++) {
                u64 key = keys_sorted[a];
                int p = a - 1;
                while (p >= s0 && keys_sorted[p] < key) {
                    keys_sorted[p + 1] = keys_sorted[p];
                    p--;
                }
                keys_sorted[p + 1] = key;
            }
        }
    }
    __syncthreads();

    const float* db = deltas + (size_t)b * IMG_N_ANC * 4;
    for (int t = tid; t < PRE_NMS; t += nt) {
        u64 key = keys_sorted[t];
        unsigned int idx = 0xFFFFFFFFu - (unsigned int)(key & 0xFFFFFFFFull);
        float score = __uint_as_float((unsigned int)(key >> 32));

        float a0 = anchors[idx * 4 + 0];
        float a1 = anchors[idx * 4 + 1];
        float a2 = anchors[idx * 4 + 2];
        float a3 = anchors[idx * 4 + 3];
        float d0 = db[(size_t)idx * 4 + 0] * 0.1f;
        float d1 = db[(size_t)idx * 4 + 1] * 0.1f;
        float d2 = db[(size_t)idx * 4 + 2] * 0.2f;
        float d3 = db[(size_t)idx * 4 + 3] * 0.2f;

        float anc_h = a2 - a0;
        float anc_w = a3 - a1;
        float ctr_y = a0 + 0.5f * anc_h;
        float ctr_x = a1 + 0.5f * anc_w;
        float bh = expf(d2) * anc_h;
        float bw = expf(d3) * anc_w;
        float bcy = d0 * anc_h + ctr_y;
        float bcx = d1 * anc_w + ctr_x;
        float y1 = bcy - 0.5f * bh;
        float x1 = bcx - 0.5f * bw;
        float y2 = y1 + bh;
        float x2 = x1 + bw;

        float ar = (y2 - y1) * (x2 - x1);
        g_y1[b][t] = y1; g_x1[b][t] = x1;
        g_y2[b][t] = y2; g_x2[b][t] = x2;
        g_ar[b][t] = ar;
        g_cs[b][t] = ar * (IOU_THR / (1.0f + IOU_THR));
        g_sc[b][t] = score;
    }
}

// ================= Kernel B: forward suppression bit-matrix =================
// Proven R9 body; grid (94, 24, GRP), batch = b0 + blockIdx.z.
__device__ __forceinline__ bool iou_exact_hit(float ry1, float rx1, float ry2,
                                              float rx2, float rar,
                                              float4 c4, float ca)
{
    float ih = fmaxf(fminf(ry2, c4.z) - fmaxf(ry1, c4.x), 0.0f);
    float iw = fmaxf(fminf(rx2, c4.w) - fmaxf(rx1, c4.y), 0.0f);
    float inter = __fmul_rn(ih, iw);
    float dd = __fadd_rn(__fadd_rn(__fadd_rn(rar, ca), -inter), 1e-8f);
    return __fdiv_rn(inter, dd) > IOU_THR;
}

__global__ __launch_bounds__(64)
void iou_matrix_kernel(int b0)
{
    const int cb = blockIdx.x;
    const int rb = blockIdx.y;
    if (cb < rb * 4) return;
    const int b   = b0 + blockIdx.z;
    const int tid = threadIdx.x;

    __shared__ float4 cbox[64];
    __shared__ float  cncs[64];
    __shared__ float  care[64];

    const int j0 = cb * 64;
    {
        int j = j0 + tid;
        if (j < PRE_NMS) {
            cbox[tid] = make_float4(g_y1[b][j], g_x1[b][j], g_y2[b][j], g_x2[b][j]);
            cncs[tid] = -g_cs[b][j];
            care[tid] = g_ar[b][j];
        } else {
            cbox[tid] = make_float4(0.f, 0.f, 0.f, 0.f);
            cncs[tid] = 0.f;
            care[tid] = 0.f;
        }
    }
    __syncthreads();

    float ry1[4], rx1[4], ry2[4], rx2[4], rncs[4], rar[4];
    #pragma unroll
    for (int r = 0; r < 4; r++) {
        int i = rb * 256 + r * 64 + tid;
        int ii = (i < PRE_NMS) ? i : 0;
        ry1[r] = g_y1[b][ii]; rx1[r] = g_x1[b][ii];
        ry2[r] = g_y2[b][ii]; rx2[r] = g_x2[b][ii];
        rncs[r] = -g_cs[b][ii]; rar[r] = g_ar[b][ii];
    }

    unsigned int bhi[4] = {0,0,0,0}, blo[4] = {0,0,0,0};
    unsigned int fhi[4] = {0,0,0,0}, flo[4] = {0,0,0,0};

    #pragma unroll 8
    for (int j = 63; j >= 32; j--) {
        float4 c4 = cbox[j];
        float ncc = cncs[j];
        #pragma unroll
        for (int r = 0; r < 4; r++) {
            float ih = fmaxf(fminf(ry2[r], c4.z) - fmaxf(ry1[r], c4.x), 0.0f);
            float iw = fmaxf(fminf(rx2[r], c4.w) - fmaxf(rx1[r], c4.y), 0.0f);
            float nss  = rncs[r] + ncc;
            float diff = fmaf(ih, iw, nss);
            float nthr = fmaf(1e-4f, nss, -1e-8f);
            float t    = fabsf(diff) + nthr;
            bhi[r] = (bhi[r] << 1) | (diff > 0.0f ? 1u : 0u);
            fhi[r] = (fhi[r] << 1) | (t <= 0.0f ? 1u : 0u);
        }
    }
    #pragma unroll 8
    for (int j = 31; j >= 0; j--) {
        float4 c4 = cbox[j];
        float ncc = cncs[j];
        #pragma unroll
        for (int r = 0; r < 4; r++) {
            float ih = fmaxf(fminf(ry2[r], c4.z) - fmaxf(ry1[r], c4.x), 0.0f);
            float iw = fmaxf(fminf(rx2[r], c4.w) - fmaxf(rx1[r], c4.y), 0.0f);
            float nss  = rncs[r] + ncc;
            float diff = fmaf(ih, iw, nss);
            float nthr = fmaf(1e-4f, nss, -1e-8f);
            float t    = fabsf(diff) + nthr;
            blo[r] = (blo[r] << 1) | (diff > 0.0f ? 1u : 0u);
            flo[r] = (flo[r] << 1) | (t <= 0.0f ? 1u : 0u);
        }
    }

    #pragma unroll
    for (int r = 0; r < 4; r++) {
        unsigned int f = flo[r];
        while (f) {
            int j = __ffs(f) - 1; f &= f - 1u;
            bool hit = iou_exact_hit(ry1[r], rx1[r], ry2[r], rx2[r], rar[r],
                                     cbox[j], care[j]);
            blo[r] = hit ? (blo[r] | (1u << j)) : (blo[r] & ~(1u << j));
        }
        f = fhi[r];
        while (f) {
            int j = __ffs(f) - 1; f &= f - 1u;
            bool hit = iou_exact_hit(ry1[r], rx1[r], ry2[r], rx2[r], rar[r],
                                     cbox[j + 32], care[j + 32]);
            bhi[r] = hit ? (bhi[r] | (1u << j)) : (bhi[r] & ~(1u << j));
        }
    }

    #pragma unroll
    for (int r = 0; r < 4; r++) {
        int i = rb * 256 + r * 64 + tid;
        if (i < PRE_NMS && cb >= (i >> 6)) {
            u64 bits = ((u64)bhi[r] << 32) | (u64)blo[r];
            int dlt = i - j0;
            u64 m = (dlt < 0) ? ~0ull : ((dlt >= 63) ? 0ull : (~0ull << (dlt + 1)));
            g_masks[b][i][cb] = bits & m;
        }
    }
}

// ================= Kernel C: greedy bit-reduce + output ====================
// Proven R9 body; grid = GRP, batch = b0 + blockIdx.x.
#define C_NT 512

__global__ __launch_bounds__(C_NT, 1)
void nms_reduce_kernel(float* __restrict__ out, int b0)
{
    const int b   = b0 + blockIdx.x;
    const int tid = threadIdx.x;

    __shared__ u64 s_diag[64];
    __shared__ u64 s_pub[4];
    __shared__ int s_rows[64];
    __shared__ int s_nk;

    float* ob = out + (size_t)b * POST_NMS * 4;
    float* os = out + (size_t)BATCH * POST_NMS * 4 + (size_t)b * POST_NMS;

    for (int t = tid; t < POST_NMS * 4; t += C_NT) ob[t] = 0.0f;
    for (int t = tid; t < POST_NMS; t += C_NT)     os[t] = 0.0f;

    const int w   = tid >> 2;
    const int sub = tid & 3;
    u64 rem = 0ull;

    if (tid >= 448) s_diag[tid - 448] = g_masks[b][tid - 448][0];
    if (tid < 4) s_pub[tid] = 0ull;
    __syncthreads();

    int cnt = 0;
    for (int c = 0; c < NW; c++) {
        if (tid == 0) {
            u64 remc = s_pub[0] | s_pub[1] | s_pub[2] | s_pub[3];
            int lim = PRE_NMS - c * 64;
            u64 alive = ~remc;
            if (lim < 64) alive &= ((1ull << lim) - 1ull);
            int nk = 0, cc = cnt;
            while (alive && cc < POST_NMS) {
                int i = __ffsll((long long)alive) - 1;
                s_rows[nk++] = c * 64 + i;
                cc++;
                alive &= ~(s_diag[i] | (1ull << i));
            }
            s_nk = nk;
        }
        __syncthreads();
        const int nk = s_nk;

        if (tid < nk) {
            int r    = s_rows[tid];
            int rank = cnt + tid;
            ob[rank * 4 + 0] = fminf(fmaxf(g_y1[b][r], 0.0f), 1.0f);
            ob[rank * 4 + 1] = fminf(fmaxf(g_x1[b][r], 0.0f), 1.0f);
            ob[rank * 4 + 2] = fminf(fmaxf(g_y2[b][r], 0.0f), 1.0f);
            ob[rank * 4 + 3] = fminf(fmaxf(g_x2[b][r], 0.0f), 1.0f);
            os[rank] = g_sc[b][r];
        }

        if (tid < 376 && w > c) {
            #pragma unroll 4
            for (int m = sub; m < nk; m += 4) rem |= g_masks[b][s_rows[m]][w];
        }

        if (c + 1 < NW && tid >= 448) {
            int row = (c + 1) * 64 + (tid - 448);
            s_diag[tid - 448] = (row < PRE_NMS) ? g_masks[b][row][c + 1] : 0ull;
        }

        if (tid < 376 && w == c + 1) s_pub[sub] = rem;

        cnt += nk;
        __syncthreads();
        if (cnt >= POST_NMS) break;
    }
}

// ============================== launch =====================================
// Fork-join overlap: B group g (full chip) on the launch stream; C group g
// (GRP CTAs) on a non-blocking side stream gated by an event after B_g.
// C_0..C_2 overlap with B_1..B_3; only C_3 remains on the critical path.
// Streams/events are host objects created once — no device memory involved.
extern "C" void kernel_launch(void* const* d_in, const int* in_sizes, int n_in,
                              void* d_out, int out_size) {
    const float* deltas  = (const float*)d_in[0];
    const float* probs   = (const float*)d_in[1];
    const float* anchors = (const float*)d_in[2];
    float* out = (float*)d_out;

    static cudaStream_t s_side = nullptr;
    static cudaEvent_t  s_fork[NGRP];
    static cudaEvent_t  s_join[NGRP];
    if (s_side == nullptr) {
        cudaStreamCreateWithFlags(&s_side, cudaStreamNonBlocking);
        for (int g = 0; g < NGRP; g++) {
            cudaEventCreateWithFlags(&s_fork[g], cudaEventDisableTiming);
            cudaEventCreateWithFlags(&s_join[g], cudaEventDisableTiming);
        }
        cudaFuncSetAttribute(sort_decode_kernel,
                             cudaFuncAttributeMaxDynamicSharedMemorySize,
                             A_SMEM_TOTAL);
    }

    sort_decode_kernel<<<BATCH, A_NT, A_SMEM_TOTAL>>>(deltas, probs, anchors);

    for (int g = 0; g < NGRP; g++) {
        iou_matrix_kernel<<<dim3(NW, 24, GRP), 64>>>(g * GRP);
        cudaEventRecord(s_fork[g], 0);
        cudaStreamWaitEvent(s_side, s_fork[g], 0);
        nms_reduce_kernel<<<GRP, C_NT, 0, s_side>>>(out, g * GRP);
        cudaEventRecord(s_join[g], s_side);
    }
    for (int g = 0; g < NGRP; g++) {
        cudaStreamWaitEvent(0, s_join[g], 0);
    }
}

// round 11
// speedup vs baseline: 1.6368x; 1.6368x over previous
#include <cuda_runtime.h>
#include <cuda_bf16.h>
#include <cstdint>

#define IMG_N_ANC   8649      // 31*31*9
#define PRE_NMS     6000
#define POST_NMS    1500
#define IOU_THR     0.7f
#define BATCH       16
#define NW          94        // 94 u64 words cover 6016 >= 6000 cols
#define NWP         96        // padded row stride (768 B)
#define NPAD        6016
#define NBIN        2048
#define NKEY        8704      // padded key capacity (>= 8649)

typedef unsigned long long u64;

// ---------------- device scratch (static; no allocations) ----------------
__device__ u64   g_masks[BATCH][NPAD][NWP];   // [b][row][word], ~73.9 MB
__device__ float g_y1[BATCH][NPAD];
__device__ float g_x1[BATCH][NPAD];
__device__ float g_y2[BATCH][NPAD];
__device__ float g_x2[BATCH][NPAD];
__device__ float g_ar[BATCH][NPAD];
__device__ float g_cs[BATCH][NPAD];           // ar * (0.7/1.7)
__device__ float g_sc[BATCH][NPAD];

// ================= Kernel A: bucket sort + decode top-6000 =================
#define A_NT          1024
#define A_OFF_RAW     0
#define A_OFF_SORT    (NKEY * 8)
#define A_OFF_HIST    (A_OFF_SORT + NKEY * 8)
#define A_OFF_START   (A_OFF_HIST + NBIN * 4)
#define A_SMEM_TOTAL  (A_OFF_START + NBIN * 4)

__global__ __launch_bounds__(A_NT, 1)
void sort_decode_kernel(const float* __restrict__ deltas,
                        const float* __restrict__ probs,
                        const float* __restrict__ anchors)
{
    extern __shared__ char smem[];
    u64* keys_raw    = (u64*)(smem + A_OFF_RAW);
    u64* keys_sorted = (u64*)(smem + A_OFF_SORT);
    unsigned int* hist  = (unsigned int*)(smem + A_OFF_HIST);
    unsigned int* start = (unsigned int*)(smem + A_OFF_START);

    const int b   = blockIdx.x;
    const int tid = threadIdx.x;
    const int nt  = A_NT;

    for (int i = tid; i < NBIN; i += nt) hist[i] = 0u;
    __syncthreads();

    const float* pb = probs + (size_t)b * IMG_N_ANC;
    for (int i = tid; i < IMG_N_ANC; i += nt) {
        float s = pb[i];
        unsigned int bits = __float_as_uint(s);
        u64 k = ((u64)bits << 32) | (u64)(0xFFFFFFFFu - (unsigned)i);
        keys_raw[i] = k;
        int bin = (int)(s * (float)NBIN);
        bin = max(0, min(NBIN - 1, bin));
        atomicAdd(&hist[bin], 1u);
    }
    __syncthreads();

    if (tid < 32) {
        const int lane = tid;
        int part = 0;
        #pragma unroll 8
        for (int q = 0; q < 64; q++) part += (int)hist[NBIN - 1 - (lane * 64 + q)];
        int inc = part;
        #pragma unroll
        for (int off = 1; off < 32; off <<= 1) {
            int v = __shfl_up_sync(0xFFFFFFFFu, inc, off);
            if (lane >= off) inc += v;
        }
        int excl = inc - part;
        for (int q = 0; q < 64; q++) {
            int v = NBIN - 1 - (lane * 64 + q);
            start[v] = (unsigned int)excl;
            excl += (int)hist[v];
        }
    }
    __syncthreads();

    for (int i = tid; i < NBIN; i += nt) hist[i] = 0u;
    __syncthreads();

    for (int i = tid; i < IMG_N_ANC; i += nt) {
        u64 k = keys_raw[i];
        float s = __uint_as_float((unsigned int)(k >> 32));
        int bin = (int)(s * (float)NBIN);
        bin = max(0, min(NBIN - 1, bin));
        unsigned int pos = start[bin] + atomicAdd(&hist[bin], 1u);
        keys_sorted[pos] = k;
    }
    __syncthreads();

    for (int v = tid; v < NBIN; v += nt) {
        int s0 = (int)start[v];
        int c  = (int)hist[v];
        if (s0 < PRE_NMS && c > 1) {
            for (int a = s0 + 1; a < s0 + c; a++) {
                u64 key = keys_sorted[a];
                int p = a - 1;
                while (p >= s0 && keys_sorted[p] < key) {
                    keys_sorted[p + 1] = keys_sorted[p];
                    p--;
                }
                keys_sorted[p + 1] = key;
            }
        }
    }
    __syncthreads();

    const float* db = deltas + (size_t)b * IMG_N_ANC * 4;
    for (int t = tid; t < PRE_NMS; t += nt) {
        u64 key = keys_sorted[t];
        unsigned int idx = 0xFFFFFFFFu - (unsigned int)(key & 0xFFFFFFFFull);
        float score = __uint_as_float((unsigned int)(key >> 32));

        float a0 = anchors[idx * 4 + 0];
        float a1 = anchors[idx * 4 + 1];
        float a2 = anchors[idx * 4 + 2];
        float a3 = anchors[idx * 4 + 3];
        float d0 = db[(size_t)idx * 4 + 0] * 0.1f;
        float d1 = db[(size_t)idx * 4 + 1] * 0.1f;
        float d2 = db[(size_t)idx * 4 + 2] * 0.2f;
        float d3 = db[(size_t)idx * 4 + 3] * 0.2f;

        float anc_h = a2 - a0;
        float anc_w = a3 - a1;
        float ctr_y = a0 + 0.5f * anc_h;
        float ctr_x = a1 + 0.5f * anc_w;
        float bh = expf(d2) * anc_h;
        float bw = expf(d3) * anc_w;
        float bcy = d0 * anc_h + ctr_y;
        float bcx = d1 * anc_w + ctr_x;
        float y1 = bcy - 0.5f * bh;
        float x1 = bcx - 0.5f * bw;
        float y2 = y1 + bh;
        float x2 = x1 + bw;

        float ar = (y2 - y1) * (x2 - x1);
        g_y1[b][t] = y1; g_x1[b][t] = x1;
        g_y2[b][t] = y2; g_x2[b][t] = x2;
        g_ar[b][t] = ar;
        g_cs[b][t] = ar * (IOU_THR / (1.0f + IOU_THR));
        g_sc[b][t] = score;
    }
}

// ================= Kernel B: forward suppression bit-matrix =================
// Proven R9 geometry: grid (94, 24, 16), 64 threads, 4 rows/thread.
// Bit accumulate via b*2+bit (IMAD, fma pipe) to offload the ALU pipe.
__device__ __forceinline__ bool iou_exact_hit(float ry1, float rx1, float ry2,
                                              float rx2, float rar,
                                              float4 c4, float ca)
{
    float ih = fmaxf(fminf(ry2, c4.z) - fmaxf(ry1, c4.x), 0.0f);
    float iw = fmaxf(fminf(rx2, c4.w) - fmaxf(rx1, c4.y), 0.0f);
    float inter = __fmul_rn(ih, iw);
    float dd = __fadd_rn(__fadd_rn(__fadd_rn(rar, ca), -inter), 1e-8f);
    return __fdiv_rn(inter, dd) > IOU_THR;
}

__global__ __launch_bounds__(64)
void iou_matrix_kernel()
{
    const int cb = blockIdx.x;
    const int rb = blockIdx.y;
    if (cb < rb * 4) return;
    const int b   = blockIdx.z;
    const int tid = threadIdx.x;

    __shared__ float4 cbox[64];
    __shared__ float  cncs[64];
    __shared__ float  care[64];

    const int j0 = cb * 64;
    {
        int j = j0 + tid;
        if (j < PRE_NMS) {
            cbox[tid] = make_float4(g_y1[b][j], g_x1[b][j], g_y2[b][j], g_x2[b][j]);
            cncs[tid] = -g_cs[b][j];
            care[tid] = g_ar[b][j];
        } else {
            cbox[tid] = make_float4(0.f, 0.f, 0.f, 0.f);
            cncs[tid] = 0.f;
            care[tid] = 0.f;
        }
    }
    __syncthreads();

    float ry1[4], rx1[4], ry2[4], rx2[4], rncs[4], rar[4];
    #pragma unroll
    for (int r = 0; r < 4; r++) {
        int i = rb * 256 + r * 64 + tid;
        int ii = (i < PRE_NMS) ? i : 0;
        ry1[r] = g_y1[b][ii]; rx1[r] = g_x1[b][ii];
        ry2[r] = g_y2[b][ii]; rx2[r] = g_x2[b][ii];
        rncs[r] = -g_cs[b][ii]; rar[r] = g_ar[b][ii];
    }

    unsigned int bhi[4] = {0,0,0,0}, blo[4] = {0,0,0,0};
    unsigned int fhi[4] = {0,0,0,0}, flo[4] = {0,0,0,0};

    #pragma unroll 8
    for (int j = 63; j >= 32; j--) {
        float4 c4 = cbox[j];
        float ncc = cncs[j];
        #pragma unroll
        for (int r = 0; r < 4; r++) {
            float ih = fmaxf(fminf(ry2[r], c4.z) - fmaxf(ry1[r], c4.x), 0.0f);
            float iw = fmaxf(fminf(rx2[r], c4.w) - fmaxf(rx1[r], c4.y), 0.0f);
            float nss  = rncs[r] + ncc;
            float diff = fmaf(ih, iw, nss);
            float nthr = fmaf(1e-4f, nss, -1e-8f);
            float t    = fabsf(diff) + nthr;
            bhi[r] = bhi[r] * 2u + (diff > 0.0f ? 1u : 0u);   // IMAD (fma pipe)
            fhi[r] = fhi[r] * 2u + (t <= 0.0f ? 1u : 0u);
        }
    }
    #pragma unroll 8
    for (int j = 31; j >= 0; j--) {
        float4 c4 = cbox[j];
        float ncc = cncs[j];
        #pragma unroll
        for (int r = 0; r < 4; r++) {
            float ih = fmaxf(fminf(ry2[r], c4.z) - fmaxf(ry1[r], c4.x), 0.0f);
            float iw = fmaxf(fminf(rx2[r], c4.w) - fmaxf(rx1[r], c4.y), 0.0f);
            float nss  = rncs[r] + ncc;
            float diff = fmaf(ih, iw, nss);
            float nthr = fmaf(1e-4f, nss, -1e-8f);
            float t    = fabsf(diff) + nthr;
            blo[r] = blo[r] * 2u + (diff > 0.0f ? 1u : 0u);
            flo[r] = flo[r] * 2u + (t <= 0.0f ? 1u : 0u);
        }
    }

    #pragma unroll
    for (int r = 0; r < 4; r++) {
        unsigned int f = flo[r];
        while (f) {
            int j = __ffs(f) - 1; f &= f - 1u;
            bool hit = iou_exact_hit(ry1[r], rx1[r], ry2[r], rx2[r], rar[r],
                                     cbox[j], care[j]);
            blo[r] = hit ? (blo[r] | (1u << j)) : (blo[r] & ~(1u << j));
        }
        f = fhi[r];
        while (f) {
            int j = __ffs(f) - 1; f &= f - 1u;
            bool hit = iou_exact_hit(ry1[r], rx1[r], ry2[r], rx2[r], rar[r],
                                     cbox[j + 32], care[j + 32]);
            bhi[r] = hit ? (bhi[r] | (1u << j)) : (bhi[r] & ~(1u << j));
        }
    }

    #pragma unroll
    for (int r = 0; r < 4; r++) {
        int i = rb * 256 + r * 64 + tid;
        if (i < PRE_NMS && cb >= (i >> 6)) {
            u64 bits = ((u64)bhi[r] << 32) | (u64)blo[r];
            int dlt = i - j0;
            u64 m = (dlt < 0) ? ~0ull : ((dlt >= 63) ? 0ull : (~0ull << (dlt + 1)));
            g_masks[b][i][cb] = bits & m;
        }
    }
}

// ================= Kernel C: greedy bit-reduce + output ====================
// 512 threads; 4-way co-owned words. NEW: speculative mask loads for the
// first 32 alive rows issued BEFORE the serial resolve (loads overlap the
// resolve); diag double-buffered and prefetched in the same window. Rows
// beyond the 32-covered window (early chunks only) use a post-resolve load.
#define C_NT 512
#define SPECD 8    // spec loads per owner thread (4 owners -> 32 rows covered)

__global__ __launch_bounds__(C_NT, 1)
void nms_reduce_kernel(float* __restrict__ out)
{
    const int b   = blockIdx.x;
    const int tid = threadIdx.x;

    __shared__ u64 s_diag[2][64];
    __shared__ u64 s_pub[4];
    __shared__ u64 s_keptmask;
    __shared__ int s_rows[64];
    __shared__ int s_nk;

    float* ob = out + (size_t)b * POST_NMS * 4;
    float* os = out + (size_t)BATCH * POST_NMS * 4 + (size_t)b * POST_NMS;

    for (int t = tid; t < POST_NMS * 4; t += C_NT) ob[t] = 0.0f;
    for (int t = tid; t < POST_NMS; t += C_NT)     os[t] = 0.0f;

    const int w   = tid >> 2;        // owned word (valid when tid < 376)
    const int sub = tid & 3;
    u64 rem = 0ull;

    if (tid >= 448) s_diag[0][tid - 448] = g_masks[b][tid - 448][0];
    if (tid < 4) s_pub[tid] = 0ull;
    __syncthreads();

    int cnt = 0;
    for (int c = 0; c < NW; c++) {
        // alive for this chunk is known NOW (published last iteration)
        u64 remc = s_pub[0] | s_pub[1] | s_pub[2] | s_pub[3];
        int lim = PRE_NMS - c * 64;
        u64 alive = ~remc;
        if (lim < 64) alive &= ((1ull << lim) - 1ull);

        // --- speculative loads: masks of first 32 alive rows, 8 per owner ---
        u64 spec[SPECD];
        int specbit[SPECD];
        const bool owner = (tid < 376) && (w > c);
        {
            u64 aa = alive;
            // drop lowest `sub` set bits
            for (int k = 0; k < sub; k++) aa &= aa - 1ull;
            #pragma unroll
            for (int q = 0; q < SPECD; q++) {
                int bit = aa ? (__ffsll((long long)aa) - 1) : -1;
                specbit[q] = bit;
                spec[q] = (owner && bit >= 0) ? g_masks[b][c * 64 + bit][w] : 0ull;
                aa &= aa - 1ull; aa &= aa - 1ull;      // drop 4 set bits
                aa &= aa - 1ull; aa &= aa - 1ull;
            }
        }

        // --- diag prefetch for c+1 (double-buffered; overlaps resolve) ---
        if (c + 1 < NW && tid >= 448) {
            int row = (c + 1) * 64 + (tid - 448);
            s_diag[(c + 1) & 1][tid - 448] =
                (row < PRE_NMS) ? g_masks[b][row][c + 1] : 0ull;
        }

        // --- serial resolve (loads above are in flight) ---
        if (tid == 0) {
            u64 av = alive;
            u64 kept = 0ull;
            int nk = 0, cc = cnt;
            while (av && cc < POST_NMS) {
                int i = __ffsll((long long)av) - 1;
                s_rows[nk++] = c * 64 + i;
                kept |= (1ull << i);
                cc++;
                av &= ~(s_diag[c & 1][i] | (1ull << i));
            }
            s_nk = nk;
            s_keptmask = kept;
        }
        __syncthreads();
        const int nk = s_nk;
        const u64 kept = s_keptmask;

        // emit kept boxes (rank = cnt + position)
        if (tid < nk) {
            int r    = s_rows[tid];
            int rank = cnt + tid;
            ob[rank * 4 + 0] = fminf(fmaxf(g_y1[b][r], 0.0f), 1.0f);
            ob[rank * 4 + 1] = fminf(fmaxf(g_x1[b][r], 0.0f), 1.0f);
            ob[rank * 4 + 2] = fminf(fmaxf(g_y2[b][r], 0.0f), 1.0f);
            ob[rank * 4 + 3] = fminf(fmaxf(g_x2[b][r], 0.0f), 1.0f);
            os[rank] = g_sc[b][r];
        }

        if (owner) {
            // fast path: OR spec entries whose row was kept
            #pragma unroll
            for (int q = 0; q < SPECD; q++) {
                if (specbit[q] >= 0 && ((kept >> specbit[q]) & 1ull))
                    rem |= spec[q];
            }
            // slow path: kept rows beyond the 32 covered alive bits
            if (__popcll(alive) > 32) {
                u64 x = alive;
                #pragma unroll
                for (int k = 0; k < 32; k++) x &= x - 1ull;   // drop 32 lowest
                x &= kept;
                int m = 0;
                while (x) {
                    int t = __ffsll((long long)x) - 1; x &= x - 1ull;
                    if ((m & 3) == sub) rem |= g_masks[b][c * 64 + t][w];
                    m++;
                }
            }
            // publish next chunk's suppression word
            if (w == c + 1) s_pub[sub] = rem;
        }

        cnt += nk;
        __syncthreads();
        if (cnt >= POST_NMS) break;
    }
}

// ============================== launch =====================================
extern "C" void kernel_launch(void* const* d_in, const int* in_sizes, int n_in,
                              void* d_out, int out_size) {
    const float* deltas  = (const float*)d_in[0];
    const float* probs   = (const float*)d_in[1];
    const float* anchors = (const float*)d_in[2];
    float* out = (float*)d_out;

    cudaFuncSetAttribute(sort_decode_kernel,
                         cudaFuncAttributeMaxDynamicSharedMemorySize, A_SMEM_TOTAL);

    sort_decode_kernel<<<BATCH, A_NT, A_SMEM_TOTAL>>>(deltas, probs, anchors);
    iou_matrix_kernel<<<dim3(NW, 24, BATCH), 64>>>();
    nms_reduce_kernel<<<BATCH, C_NT>>>(out);
}

// round 12
// speedup vs baseline: 1.9656x; 1.2009x over previous
#include <cuda_runtime.h>
#include <cuda_bf16.h>
#include <cstdint>

#define IMG_N_ANC   8649      // 31*31*9
#define PRE_NMS     6000
#define POST_NMS    1500
#define IOU_THR     0.7f
#define BATCH       16
#define NW          94        // 94 u64 words cover 6016 >= 6000 cols
#define NWP         96        // padded row stride (768 B)
#define NPAD        6016
#define NBIN        2048
#define NKEY        8704      // padded key capacity (>= 8649)

typedef unsigned long long u64;

// ---------------- device scratch (static; no allocations) ----------------
__device__ u64   g_masks[BATCH][NPAD][NWP];   // [b][row][word], ~73.9 MB
__device__ float g_y1[BATCH][NPAD];
__device__ float g_x1[BATCH][NPAD];
__device__ float g_y2[BATCH][NPAD];
__device__ float g_x2[BATCH][NPAD];
__device__ float g_ar[BATCH][NPAD];
__device__ float g_cs[BATCH][NPAD];           // ar * (0.7/1.7)
__device__ float g_sc[BATCH][NPAD];

// ================= Kernel A: bucket sort + decode top-6000 =================
#define A_NT          1024
#define A_OFF_RAW     0
#define A_OFF_SORT    (NKEY * 8)
#define A_OFF_HIST    (A_OFF_SORT + NKEY * 8)
#define A_OFF_START   (A_OFF_HIST + NBIN * 4)
#define A_SMEM_TOTAL  (A_OFF_START + NBIN * 4)

__global__ __launch_bounds__(A_NT, 1)
void sort_decode_kernel(const float* __restrict__ deltas,
                        const float* __restrict__ probs,
                        const float* __restrict__ anchors)
{
    extern __shared__ char smem[];
    u64* keys_raw    = (u64*)(smem + A_OFF_RAW);
    u64* keys_sorted = (u64*)(smem + A_OFF_SORT);
    unsigned int* hist  = (unsigned int*)(smem + A_OFF_HIST);
    unsigned int* start = (unsigned int*)(smem + A_OFF_START);

    const int b   = blockIdx.x;
    const int tid = threadIdx.x;
    const int nt  = A_NT;

    for (int i = tid; i < NBIN; i += nt) hist[i] = 0u;
    __syncthreads();

    const float* pb = probs + (size_t)b * IMG_N_ANC;
    for (int i = tid; i < IMG_N_ANC; i += nt) {
        float s = pb[i];
        unsigned int bits = __float_as_uint(s);
        u64 k = ((u64)bits << 32) | (u64)(0xFFFFFFFFu - (unsigned)i);
        keys_raw[i] = k;
        int bin = (int)(s * (float)NBIN);
        bin = max(0, min(NBIN - 1, bin));
        atomicAdd(&hist[bin], 1u);
    }
    __syncthreads();

    if (tid < 32) {
        const int lane = tid;
        int part = 0;
        #pragma unroll 8
        for (int q = 0; q < 64; q++) part += (int)hist[NBIN - 1 - (lane * 64 + q)];
        int inc = part;
        #pragma unroll
        for (int off = 1; off < 32; off <<= 1) {
            int v = __shfl_up_sync(0xFFFFFFFFu, inc, off);
            if (lane >= off) inc += v;
        }
        int excl = inc - part;
        for (int q = 0; q < 64; q++) {
            int v = NBIN - 1 - (lane * 64 + q);
            start[v] = (unsigned int)excl;
            excl += (int)hist[v];
        }
    }
    __syncthreads();

    for (int i = tid; i < NBIN; i += nt) hist[i] = 0u;
    __syncthreads();

    for (int i = tid; i < IMG_N_ANC; i += nt) {
        u64 k = keys_raw[i];
        float s = __uint_as_float((unsigned int)(k >> 32));
        int bin = (int)(s * (float)NBIN);
        bin = max(0, min(NBIN - 1, bin));
        unsigned int pos = start[bin] + atomicAdd(&hist[bin], 1u);
        keys_sorted[pos] = k;
    }
    __syncthreads();

    for (int v = tid; v < NBIN; v += nt) {
        int s0 = (int)start[v];
        int c  = (int)hist[v];
        if (s0 < PRE_NMS && c > 1) {
            for (int a = s0 + 1; a < s0 + c; a++) {
                u64 key = keys_sorted[a];
                int p = a - 1;
                while (p >= s0 && keys_sorted[p] < key) {
                    keys_sorted[p + 1] = keys_sorted[p];
                    p--;
                }
                keys_sorted[p + 1] = key;
            }
        }
    }
    __syncthreads();

    const float* db = deltas + (size_t)b * IMG_N_ANC * 4;
    for (int t = tid; t < PRE_NMS; t += nt) {
        u64 key = keys_sorted[t];
        unsigned int idx = 0xFFFFFFFFu - (unsigned int)(key & 0xFFFFFFFFull);
        float score = __uint_as_float((unsigned int)(key >> 32));

        float a0 = anchors[idx * 4 + 0];
        float a1 = anchors[idx * 4 + 1];
        float a2 = anchors[idx * 4 + 2];
        float a3 = anchors[idx * 4 + 3];
        float d0 = db[(size_t)idx * 4 + 0] * 0.1f;
        float d1 = db[(size_t)idx * 4 + 1] * 0.1f;
        float d2 = db[(size_t)idx * 4 + 2] * 0.2f;
        float d3 = db[(size_t)idx * 4 + 3] * 0.2f;

        float anc_h = a2 - a0;
        float anc_w = a3 - a1;
        float ctr_y = a0 + 0.5f * anc_h;
        float ctr_x = a1 + 0.5f * anc_w;
        float bh = expf(d2) * anc_h;
        float bw = expf(d3) * anc_w;
        float bcy = d0 * anc_h + ctr_y;
        float bcx = d1 * anc_w + ctr_x;
        float y1 = bcy - 0.5f * bh;
        float x1 = bcx - 0.5f * bw;
        float y2 = y1 + bh;
        float x2 = x1 + bw;

        float ar = (y2 - y1) * (x2 - x1);
        g_y1[b][t] = y1; g_x1[b][t] = x1;
        g_y2[b][t] = y2; g_x2[b][t] = x2;
        g_ar[b][t] = ar;
        g_cs[b][t] = ar * (IOU_THR / (1.0f + IOU_THR));
        g_sc[b][t] = score;
    }
}

// ================= Kernel B: forward suppression bit-matrix =================
// R9 geometry and accumulate (proven). Single delta: iw is NOT clamped to 0.
// Safe because ih >= 0: iw<0 forces diff <= -ssum <= 0 (no hit), matching the
// reference (clamped inter=0 -> IoU 0). Degenerate ssum~0 cases fall in the
// band (abs floor 1e-8) and take the exact fallback, which uses both clamps.
__device__ __forceinline__ bool iou_exact_hit(float ry1, float rx1, float ry2,
                                              float rx2, float rar,
                                              float4 c4, float ca)
{
    float ih = fmaxf(fminf(ry2, c4.z) - fmaxf(ry1, c4.x), 0.0f);
    float iw = fmaxf(fminf(rx2, c4.w) - fmaxf(rx1, c4.y), 0.0f);
    float inter = __fmul_rn(ih, iw);
    float dd = __fadd_rn(__fadd_rn(__fadd_rn(rar, ca), -inter), 1e-8f);
    return __fdiv_rn(inter, dd) > IOU_THR;
}

__global__ __launch_bounds__(64)
void iou_matrix_kernel()
{
    const int cb = blockIdx.x;
    const int rb = blockIdx.y;
    if (cb < rb * 4) return;
    const int b   = blockIdx.z;
    const int tid = threadIdx.x;

    __shared__ float4 cbox[64];
    __shared__ float  cncs[64];
    __shared__ float  care[64];

    const int j0 = cb * 64;
    {
        int j = j0 + tid;
        if (j < PRE_NMS) {
            cbox[tid] = make_float4(g_y1[b][j], g_x1[b][j], g_y2[b][j], g_x2[b][j]);
            cncs[tid] = -g_cs[b][j];
            care[tid] = g_ar[b][j];
        } else {
            cbox[tid] = make_float4(0.f, 0.f, 0.f, 0.f);
            cncs[tid] = 0.f;
            care[tid] = 0.f;
        }
    }
    __syncthreads();

    float ry1[4], rx1[4], ry2[4], rx2[4], rncs[4], rar[4];
    #pragma unroll
    for (int r = 0; r < 4; r++) {
        int i = rb * 256 + r * 64 + tid;
        int ii = (i < PRE_NMS) ? i : 0;
        ry1[r] = g_y1[b][ii]; rx1[r] = g_x1[b][ii];
        ry2[r] = g_y2[b][ii]; rx2[r] = g_x2[b][ii];
        rncs[r] = -g_cs[b][ii]; rar[r] = g_ar[b][ii];
    }

    unsigned int bhi[4] = {0,0,0,0}, blo[4] = {0,0,0,0};
    unsigned int fhi[4] = {0,0,0,0}, flo[4] = {0,0,0,0};

    #pragma unroll 8
    for (int j = 63; j >= 32; j--) {
        float4 c4 = cbox[j];
        float ncc = cncs[j];
        #pragma unroll
        for (int r = 0; r < 4; r++) {
            float ih = fmaxf(fminf(ry2[r], c4.z) - fmaxf(ry1[r], c4.x), 0.0f);
            float iw = fminf(rx2[r], c4.w) - fmaxf(rx1[r], c4.y);   // no 0-clamp
            float nss  = rncs[r] + ncc;
            float diff = fmaf(ih, iw, nss);
            float nthr = fmaf(1e-4f, nss, -1e-8f);
            float t    = fabsf(diff) + nthr;
            bhi[r] = (bhi[r] << 1) | (diff > 0.0f ? 1u : 0u);
            fhi[r] = (fhi[r] << 1) | (t <= 0.0f ? 1u : 0u);
        }
    }
    #pragma unroll 8
    for (int j = 31; j >= 0; j--) {
        float4 c4 = cbox[j];
        float ncc = cncs[j];
        #pragma unroll
        for (int r = 0; r < 4; r++) {
            float ih = fmaxf(fminf(ry2[r], c4.z) - fmaxf(ry1[r], c4.x), 0.0f);
            float iw = fminf(rx2[r], c4.w) - fmaxf(rx1[r], c4.y);   // no 0-clamp
            float nss  = rncs[r] + ncc;
            float diff = fmaf(ih, iw, nss);
            float nthr = fmaf(1e-4f, nss, -1e-8f);
            float t    = fabsf(diff) + nthr;
            blo[r] = (blo[r] << 1) | (diff > 0.0f ? 1u : 0u);
            flo[r] = (flo[r] << 1) | (t <= 0.0f ? 1u : 0u);
        }
    }

    #pragma unroll
    for (int r = 0; r < 4; r++) {
        unsigned int f = flo[r];
        while (f) {
            int j = __ffs(f) - 1; f &= f - 1u;
            bool hit = iou_exact_hit(ry1[r], rx1[r], ry2[r], rx2[r], rar[r],
                                     cbox[j], care[j]);
            blo[r] = hit ? (blo[r] | (1u << j)) : (blo[r] & ~(1u << j));
        }
        f = fhi[r];
        while (f) {
            int j = __ffs(f) - 1; f &= f - 1u;
            bool hit = iou_exact_hit(ry1[r], rx1[r], ry2[r], rx2[r], rar[r],
                                     cbox[j + 32], care[j + 32]);
            bhi[r] = hit ? (bhi[r] | (1u << j)) : (bhi[r] & ~(1u << j));
        }
    }

    #pragma unroll
    for (int r = 0; r < 4; r++) {
        int i = rb * 256 + r * 64 + tid;
        if (i < PRE_NMS && cb >= (i >> 6)) {
            u64 bits = ((u64)bhi[r] << 32) | (u64)blo[r];
            int dlt = i - j0;
            u64 m = (dlt < 0) ? ~0ull : ((dlt >= 63) ? 0ull : (~0ull << (dlt + 1)));
            g_masks[b][i][cb] = bits & m;
        }
    }
}

// ================= Kernel C: greedy bit-reduce + output ====================
// R9 structure. Single delta: the 4 PUBLISHER threads (w == c+1) pre-load
// masks for all alive rows of chunk c before the resolve (<=16 loads each,
// unrolled into registers), OR the kept subset after, and publish — taking
// the publisher's load latency off the per-chunk critical path. All other
// owners keep R9's post-resolve loads.
#define C_NT 512

__global__ __launch_bounds__(C_NT, 1)
void nms_reduce_kernel(float* __restrict__ out)
{
    const int b   = blockIdx.x;
    const int tid = threadIdx.x;

    __shared__ u64 s_diag[64];
    __shared__ u64 s_pub[4];
    __shared__ u64 s_keptmask;
    __shared__ int s_rows[64];
    __shared__ int s_nk;

    float* ob = out + (size_t)b * POST_NMS * 4;
    float* os = out + (size_t)BATCH * POST_NMS * 4 + (size_t)b * POST_NMS;

    for (int t = tid; t < POST_NMS * 4; t += C_NT) ob[t] = 0.0f;
    for (int t = tid; t < POST_NMS; t += C_NT)     os[t] = 0.0f;

    const int w   = tid >> 2;        // owned word (valid when tid < 376)
    const int sub = tid & 3;
    u64 rem = 0ull;

    if (tid >= 448) s_diag[tid - 448] = g_masks[b][tid - 448][0];
    if (tid < 4) s_pub[tid] = 0ull;
    __syncthreads();

    int cnt = 0;
    for (int c = 0; c < NW; c++) {
        // alive for this chunk (s_pub written last iteration, barrier-ordered)
        u64 remc = s_pub[0] | s_pub[1] | s_pub[2] | s_pub[3];
        int lim = PRE_NMS - c * 64;
        u64 alive = ~remc;
        if (lim < 64) alive &= ((1ull << lim) - 1ull);

        // publisher speculation: 4 threads (w == c+1) cover ALL alive rows
        const bool is_pub = (tid < 376) && (w == c + 1);
        u64 spec[16];
        int specbit[16];
        if (is_pub) {
            u64 aa = alive;
            for (int k = 0; k < sub; k++) aa &= aa - 1ull;
            #pragma unroll
            for (int q = 0; q < 16; q++) {
                int bit = aa ? (__ffsll((long long)aa) - 1) : -1;
                specbit[q] = bit;
                spec[q] = (bit >= 0) ? g_masks[b][c * 64 + bit][w] : 0ull;
                aa &= aa - 1ull; aa &= aa - 1ull;   // advance 4 set bits
                aa &= aa - 1ull; aa &= aa - 1ull;
            }
        }

        // serial resolve (tid0); publisher loads are in flight meanwhile
        if (tid == 0) {
            u64 av = alive;
            u64 kept = 0ull;
            int nk = 0, cc = cnt;
            while (av && cc < POST_NMS) {
                int i = __ffsll((long long)av) - 1;
                s_rows[nk++] = c * 64 + i;
                kept |= (1ull << i);
                cc++;
                av &= ~(s_diag[i] | (1ull << i));
            }
            s_nk = nk;
            s_keptmask = kept;
        }
        __syncthreads();
        const int nk = s_nk;
        const u64 kept = s_keptmask;

        // emit kept boxes (rank = cnt + position)
        if (tid < nk) {
            int r    = s_rows[tid];
            int rank = cnt + tid;
            ob[rank * 4 + 0] = fminf(fmaxf(g_y1[b][r], 0.0f), 1.0f);
            ob[rank * 4 + 1] = fminf(fmaxf(g_x1[b][r], 0.0f), 1.0f);
            ob[rank * 4 + 2] = fminf(fmaxf(g_y2[b][r], 0.0f), 1.0f);
            ob[rank * 4 + 3] = fminf(fmaxf(g_x2[b][r], 0.0f), 1.0f);
            os[rank] = g_sc[b][r];
        }

        // non-publisher owners: post-resolve loads (off critical path)
        if (tid < 376 && w > c + 1) {
            #pragma unroll 4
            for (int m = sub; m < nk; m += 4) rem |= g_masks[b][s_rows[m]][w];
        }

        // publisher: OR kept spec entries, then publish next chunk's word
        if (is_pub) {
            #pragma unroll
            for (int q = 0; q < 16; q++) {
                if (specbit[q] >= 0 && ((kept >> specbit[q]) & 1ull))
                    rem |= spec[q];
            }
            s_pub[sub] = rem;
        }

        // prefetch next chunk's diagonal words (current diag already consumed)
        if (c + 1 < NW && tid >= 448) {
            int row = (c + 1) * 64 + (tid - 448);
            s_diag[tid - 448] = (row < PRE_NMS) ? g_masks[b][row][c + 1] : 0ull;
        }

        cnt += nk;
        __syncthreads();
        if (cnt >= POST_NMS) break;
    }
}

// ============================== launch =====================================
extern "C" void kernel_launch(void* const* d_in, const int* in_sizes, int n_in,
                              void* d_out, int out_size) {
    const float* deltas  = (const float*)d_in[0];
    const float* probs   = (const float*)d_in[1];
    const float* anchors = (const float*)d_in[2];
    float* out = (float*)d_out;

    cudaFuncSetAttribute(sort_decode_kernel,
                         cudaFuncAttributeMaxDynamicSharedMemorySize, A_SMEM_TOTAL);

    sort_decode_kernel<<<BATCH, A_NT, A_SMEM_TOTAL>>>(deltas, probs, anchors);
    iou_matrix_kernel<<<dim3(NW, 24, BATCH), 64>>>();
    nms_reduce_kernel<<<BATCH, C_NT>>>(out);
}

// round 13
// speedup vs baseline: 2.0804x; 1.0584x over previous
#include <cuda_runtime.h>
#include <cuda_bf16.h>
#include <cstdint>

#define IMG_N_ANC   8649      // 31*31*9
#define PRE_NMS     6000
#define POST_NMS    1500
#define IOU_THR     0.7f
#define BATCH       16
#define NW          94        // 94 u64 words cover 6016 >= 6000 cols
#define NWP         96        // padded row stride (768 B)
#define NPAD        6016
#define NBIN        2048
#define NKEY        8704      // padded key capacity (>= 8649)

typedef unsigned long long u64;

// ---------------- device scratch (static; no allocations) ----------------
__device__ u64   g_masks[BATCH][NPAD][NWP];   // [b][row][word], ~73.9 MB
__device__ float g_y1[BATCH][NPAD];
__device__ float g_x1[BATCH][NPAD];
__device__ float g_y2[BATCH][NPAD];
__device__ float g_x2[BATCH][NPAD];
__device__ float g_ar[BATCH][NPAD];
__device__ float g_cs[BATCH][NPAD];           // ar * (0.7/1.7)
__device__ float g_sc[BATCH][NPAD];

// ================= Kernel A: bucket sort + decode top-6000 =================
#define A_NT          1024
#define A_OFF_RAW     0
#define A_OFF_SORT    (NKEY * 8)
#define A_OFF_HIST    (A_OFF_SORT + NKEY * 8)
#define A_OFF_START   (A_OFF_HIST + NBIN * 4)
#define A_SMEM_TOTAL  (A_OFF_START + NBIN * 4)

__global__ __launch_bounds__(A_NT, 1)
void sort_decode_kernel(const float* __restrict__ deltas,
                        const float* __restrict__ probs,
                        const float* __restrict__ anchors)
{
    extern __shared__ char smem[];
    u64* keys_raw    = (u64*)(smem + A_OFF_RAW);
    u64* keys_sorted = (u64*)(smem + A_OFF_SORT);
    unsigned int* hist  = (unsigned int*)(smem + A_OFF_HIST);
    unsigned int* start = (unsigned int*)(smem + A_OFF_START);

    const int b   = blockIdx.x;
    const int tid = threadIdx.x;
    const int nt  = A_NT;

    for (int i = tid; i < NBIN; i += nt) hist[i] = 0u;
    __syncthreads();

    const float* pb = probs + (size_t)b * IMG_N_ANC;
    for (int i = tid; i < IMG_N_ANC; i += nt) {
        float s = pb[i];
        unsigned int bits = __float_as_uint(s);
        u64 k = ((u64)bits << 32) | (u64)(0xFFFFFFFFu - (unsigned)i);
        keys_raw[i] = k;
        int bin = (int)(s * (float)NBIN);
        bin = max(0, min(NBIN - 1, bin));
        atomicAdd(&hist[bin], 1u);
    }
    __syncthreads();

    if (tid < 32) {
        const int lane = tid;
        int part = 0;
        #pragma unroll 8
        for (int q = 0; q < 64; q++) part += (int)hist[NBIN - 1 - (lane * 64 + q)];
        int inc = part;
        #pragma unroll
        for (int off = 1; off < 32; off <<= 1) {
            int v = __shfl_up_sync(0xFFFFFFFFu, inc, off);
            if (lane >= off) inc += v;
        }
        int excl = inc - part;
        for (int q = 0; q < 64; q++) {
            int v = NBIN - 1 - (lane * 64 + q);
            start[v] = (unsigned int)excl;
            excl += (int)hist[v];
        }
    }
    __syncthreads();

    for (int i = tid; i < NBIN; i += nt) hist[i] = 0u;
    __syncthreads();

    for (int i = tid; i < IMG_N_ANC; i += nt) {
        u64 k = keys_raw[i];
        float s = __uint_as_float((unsigned int)(k >> 32));
        int bin = (int)(s * (float)NBIN);
        bin = max(0, min(NBIN - 1, bin));
        unsigned int pos = start[bin] + atomicAdd(&hist[bin], 1u);
        keys_sorted[pos] = k;
    }
    __syncthreads();

    for (int v = tid; v < NBIN; v += nt) {
        int s0 = (int)start[v];
        int c  = (int)hist[v];
        if (s0 < PRE_NMS && c > 1) {
            for (int a = s0 + 1; a < s0 + c; a++) {
                u64 key = keys_sorted[a];
                int p = a - 1;
                while (p >= s0 && keys_sorted[p] < key) {
                    keys_sorted[p + 1] = keys_sorted[p];
                    p--;
                }
                keys_sorted[p + 1] = key;
            }
        }
    }
    __syncthreads();

    const float* db = deltas + (size_t)b * IMG_N_ANC * 4;
    for (int t = tid; t < PRE_NMS; t += nt) {
        u64 key = keys_sorted[t];
        unsigned int idx = 0xFFFFFFFFu - (unsigned int)(key & 0xFFFFFFFFull);
        float score = __uint_as_float((unsigned int)(key >> 32));

        float a0 = anchors[idx * 4 + 0];
        float a1 = anchors[idx * 4 + 1];
        float a2 = anchors[idx * 4 + 2];
        float a3 = anchors[idx * 4 + 3];
        float d0 = db[(size_t)idx * 4 + 0] * 0.1f;
        float d1 = db[(size_t)idx * 4 + 1] * 0.1f;
        float d2 = db[(size_t)idx * 4 + 2] * 0.2f;
        float d3 = db[(size_t)idx * 4 + 3] * 0.2f;

        float anc_h = a2 - a0;
        float anc_w = a3 - a1;
        float ctr_y = a0 + 0.5f * anc_h;
        float ctr_x = a1 + 0.5f * anc_w;
        float bh = expf(d2) * anc_h;
        float bw = expf(d3) * anc_w;
        float bcy = d0 * anc_h + ctr_y;
        float bcx = d1 * anc_w + ctr_x;
        float y1 = bcy - 0.5f * bh;
        float x1 = bcx - 0.5f * bw;
        float y2 = y1 + bh;
        float x2 = x1 + bw;

        float ar = (y2 - y1) * (x2 - x1);
        g_y1[b][t] = y1; g_x1[b][t] = x1;
        g_y2[b][t] = y2; g_x2[b][t] = x2;
        g_ar[b][t] = ar;
        g_cs[b][t] = ar * (IOU_THR / (1.0f + IOU_THR));
        g_sc[b][t] = score;
    }
}

// ================= Kernel B: forward suppression bit-matrix =================
// R12 body (proven). Grid now packs only valid triangle blocks:
// 1152 per batch (sum over rb of 94-4rb), linear id decoded to (rb, cb).
#define B_BLOCKS 1152

__device__ __forceinline__ bool iou_exact_hit(float ry1, float rx1, float ry2,
                                              float rx2, float rar,
                                              float4 c4, float ca)
{
    float ih = fmaxf(fminf(ry2, c4.z) - fmaxf(ry1, c4.x), 0.0f);
    float iw = fmaxf(fminf(rx2, c4.w) - fmaxf(rx1, c4.y), 0.0f);
    float inter = __fmul_rn(ih, iw);
    float dd = __fadd_rn(__fadd_rn(__fadd_rn(rar, ca), -inter), 1e-8f);
    return __fdiv_rn(inter, dd) > IOU_THR;
}

__global__ __launch_bounds__(64)
void iou_matrix_kernel()
{
    // decode linear block id -> (rb, cb) with cb >= 4*rb
    int t = blockIdx.x;
    int rb = 0;
    while (t >= 94 - 4 * rb) { t -= 94 - 4 * rb; rb++; }
    const int cb = 4 * rb + t;
    const int b   = blockIdx.y;
    const int tid = threadIdx.x;

    __shared__ float4 cbox[64];
    __shared__ float  cncs[64];
    __shared__ float  care[64];

    const int j0 = cb * 64;
    {
        int j = j0 + tid;
        if (j < PRE_NMS) {
            cbox[tid] = make_float4(g_y1[b][j], g_x1[b][j], g_y2[b][j], g_x2[b][j]);
            cncs[tid] = -g_cs[b][j];
            care[tid] = g_ar[b][j];
        } else {
            cbox[tid] = make_float4(0.f, 0.f, 0.f, 0.f);
            cncs[tid] = 0.f;
            care[tid] = 0.f;
        }
    }
    __syncthreads();

    float ry1[4], rx1[4], ry2[4], rx2[4], rncs[4], rar[4];
    #pragma unroll
    for (int r = 0; r < 4; r++) {
        int i = rb * 256 + r * 64 + tid;
        int ii = (i < PRE_NMS) ? i : 0;
        ry1[r] = g_y1[b][ii]; rx1[r] = g_x1[b][ii];
        ry2[r] = g_y2[b][ii]; rx2[r] = g_x2[b][ii];
        rncs[r] = -g_cs[b][ii]; rar[r] = g_ar[b][ii];
    }

    unsigned int bhi[4] = {0,0,0,0}, blo[4] = {0,0,0,0};
    unsigned int fhi[4] = {0,0,0,0}, flo[4] = {0,0,0,0};

    #pragma unroll 8
    for (int j = 63; j >= 32; j--) {
        float4 c4 = cbox[j];
        float ncc = cncs[j];
        #pragma unroll
        for (int r = 0; r < 4; r++) {
            float ih = fmaxf(fminf(ry2[r], c4.z) - fmaxf(ry1[r], c4.x), 0.0f);
            float iw = fminf(rx2[r], c4.w) - fmaxf(rx1[r], c4.y);   // no 0-clamp
            float nss  = rncs[r] + ncc;
            float diff = fmaf(ih, iw, nss);
            float nthr = fmaf(1e-4f, nss, -1e-8f);
            float t2   = fabsf(diff) + nthr;
            bhi[r] = (bhi[r] << 1) | (diff > 0.0f ? 1u : 0u);
            fhi[r] = (fhi[r] << 1) | (t2 <= 0.0f ? 1u : 0u);
        }
    }
    #pragma unroll 8
    for (int j = 31; j >= 0; j--) {
        float4 c4 = cbox[j];
        float ncc = cncs[j];
        #pragma unroll
        for (int r = 0; r < 4; r++) {
            float ih = fmaxf(fminf(ry2[r], c4.z) - fmaxf(ry1[r], c4.x), 0.0f);
            float iw = fminf(rx2[r], c4.w) - fmaxf(rx1[r], c4.y);   // no 0-clamp
            float nss  = rncs[r] + ncc;
            float diff = fmaf(ih, iw, nss);
            float nthr = fmaf(1e-4f, nss, -1e-8f);
            float t2   = fabsf(diff) + nthr;
            blo[r] = (blo[r] << 1) | (diff > 0.0f ? 1u : 0u);
            flo[r] = (flo[r] << 1) | (t2 <= 0.0f ? 1u : 0u);
        }
    }

    #pragma unroll
    for (int r = 0; r < 4; r++) {
        unsigned int f = flo[r];
        while (f) {
            int j = __ffs(f) - 1; f &= f - 1u;
            bool hit = iou_exact_hit(ry1[r], rx1[r], ry2[r], rx2[r], rar[r],
                                     cbox[j], care[j]);
            blo[r] = hit ? (blo[r] | (1u << j)) : (blo[r] & ~(1u << j));
        }
        f = fhi[r];
        while (f) {
            int j = __ffs(f) - 1; f &= f - 1u;
            bool hit = iou_exact_hit(ry1[r], rx1[r], ry2[r], rx2[r], rar[r],
                                     cbox[j + 32], care[j + 32]);
            bhi[r] = hit ? (bhi[r] | (1u << j)) : (bhi[r] & ~(1u << j));
        }
    }

    #pragma unroll
    for (int r = 0; r < 4; r++) {
        int i = rb * 256 + r * 64 + tid;
        if (i < PRE_NMS && cb >= (i >> 6)) {
            u64 bits = ((u64)bhi[r] << 32) | (u64)blo[r];
            int dlt = i - j0;
            u64 m = (dlt < 0) ? ~0ull : ((dlt >= 63) ? 0ull : (~0ull << (dlt + 1)));
            g_masks[b][i][cb] = bits & m;
        }
    }
}

// ================= Kernel C: greedy bit-reduce + output ====================
// Deferred owner ORs: loads for chunk c's kept rows are ISSUED at chunk c
// (statically-indexed predicated register array -> no barrier scoreboard
// wait) and CONSUMED at the top of chunk c+1, when they've long completed.
// Word w's partials are only needed at publish (end of chunk w-1); deferral
// by one chunk preserves that, and chunk-(w-1) rows are covered by the
// publisher speculation. Overflow beyond DEFN*4 kept rows (rare) is ORed
// synchronously.
#define C_NT 512
#define DEFN 12

__global__ __launch_bounds__(C_NT, 1)
void nms_reduce_kernel(float* __restrict__ out)
{
    const int b   = blockIdx.x;
    const int tid = threadIdx.x;

    __shared__ u64 s_diag[64];
    __shared__ u64 s_pub[4];
    __shared__ u64 s_keptmask;
    __shared__ int s_rows[64];
    __shared__ int s_nk;

    float* ob = out + (size_t)b * POST_NMS * 4;
    float* os = out + (size_t)BATCH * POST_NMS * 4 + (size_t)b * POST_NMS;

    for (int t = tid; t < POST_NMS * 4; t += C_NT) ob[t] = 0.0f;
    for (int t = tid; t < POST_NMS; t += C_NT)     os[t] = 0.0f;

    const int w   = tid >> 2;        // owned word (valid when tid < 376)
    const int sub = tid & 3;
    u64 rem = 0ull;
    u64 def[DEFN];
    #pragma unroll
    for (int q = 0; q < DEFN; q++) def[q] = 0ull;

    if (tid >= 448) s_diag[tid - 448] = g_masks[b][tid - 448][0];
    if (tid < 4) s_pub[tid] = 0ull;
    __syncthreads();

    int cnt = 0;
    for (int c = 0; c < NW; c++) {
        // alive for this chunk (s_pub written last chunk, barrier-ordered)
        u64 remc = s_pub[0] | s_pub[1] | s_pub[2] | s_pub[3];
        int lim = PRE_NMS - c * 64;
        u64 alive = ~remc;
        if (lim < 64) alive &= ((1ull << lim) - 1ull);

        // consume deferred loads issued last chunk (scoreboard already clear)
        if (tid < 376 && w > c) {
            #pragma unroll
            for (int q = 0; q < DEFN; q++) rem |= def[q];
            #pragma unroll
            for (int q = 0; q < DEFN; q++) def[q] = 0ull;
        }

        // publisher speculation: 4 threads (w == c+1) cover ALL alive rows
        const bool is_pub = (tid < 376) && (w == c + 1);
        u64 spec[16];
        int specbit[16];
        if (is_pub) {
            u64 aa = alive;
            for (int k = 0; k < sub; k++) aa &= aa - 1ull;
            #pragma unroll
            for (int q = 0; q < 16; q++) {
                int bit = aa ? (__ffsll((long long)aa) - 1) : -1;
                specbit[q] = bit;
                spec[q] = (bit >= 0) ? g_masks[b][c * 64 + bit][w] : 0ull;
                aa &= aa - 1ull; aa &= aa - 1ull;   // advance 4 set bits
                aa &= aa - 1ull; aa &= aa - 1ull;
            }
        }

        // serial resolve (tid0); publisher loads are in flight meanwhile
        if (tid == 0) {
            u64 av = alive;
            u64 kept = 0ull;
            int nk = 0, cc = cnt;
            while (av && cc < POST_NMS) {
                int i = __ffsll((long long)av) - 1;
                s_rows[nk++] = c * 64 + i;
                kept |= (1ull << i);
                cc++;
                av &= ~(s_diag[i] | (1ull << i));
            }
            s_nk = nk;
            s_keptmask = kept;
        }
        __syncthreads();
        const int nk = s_nk;
        const u64 kept = s_keptmask;

        // emit kept boxes (rank = cnt + position)
        if (tid < nk) {
            int r    = s_rows[tid];
            int rank = cnt + tid;
            ob[rank * 4 + 0] = fminf(fmaxf(g_y1[b][r], 0.0f), 1.0f);
            ob[rank * 4 + 1] = fminf(fmaxf(g_x1[b][r], 0.0f), 1.0f);
            ob[rank * 4 + 2] = fminf(fmaxf(g_y2[b][r], 0.0f), 1.0f);
            ob[rank * 4 + 3] = fminf(fmaxf(g_x2[b][r], 0.0f), 1.0f);
            os[rank] = g_sc[b][r];
        }

        // non-publisher owners: ISSUE deferred loads (consume next chunk).
        // Static indexing keeps def[] in registers; predicated-off loads
        // don't touch memory. No scoreboard wait before the barrier.
        if (tid < 376 && w > c + 1) {
            #pragma unroll
            for (int q = 0; q < DEFN; q++) {
                int m = sub + q * 4;
                bool v = (m < nk);
                int mm = v ? m : 0;
                def[q] = v ? g_masks[b][s_rows[mm]][w] : 0ull;
            }
            // rare overflow: sync OR
            for (int m = sub + DEFN * 4; m < nk; m += 4)
                rem |= g_masks[b][s_rows[m]][w];
        }

        // publisher: OR kept spec entries, then publish next chunk's word
        if (is_pub) {
            #pragma unroll
            for (int q = 0; q < 16; q++) {
                if (specbit[q] >= 0 && ((kept >> specbit[q]) & 1ull))
                    rem |= spec[q];
            }
            s_pub[sub] = rem;
        }

        // prefetch next chunk's diagonal words
        if (c + 1 < NW && tid >= 448) {
            int row = (c + 1) * 64 + (tid - 448);
            s_diag[tid - 448] = (row < PRE_NMS) ? g_masks[b][row][c + 1] : 0ull;
        }

        cnt += nk;
        __syncthreads();
        if (cnt >= POST_NMS) break;
    }
}

// ============================== launch =====================================
extern "C" void kernel_launch(void* const* d_in, const int* in_sizes, int n_in,
                              void* d_out, int out_size) {
    const float* deltas  = (const float*)d_in[0];
    const float* probs   = (const float*)d_in[1];
    const float* anchors = (const float*)d_in[2];
    float* out = (float*)d_out;

    cudaFuncSetAttribute(sort_decode_kernel,
                         cudaFuncAttributeMaxDynamicSharedMemorySize, A_SMEM_TOTAL);

    sort_decode_kernel<<<BATCH, A_NT, A_SMEM_TOTAL>>>(deltas, probs, anchors);
    iou_matrix_kernel<<<dim3(B_BLOCKS, BATCH), 64>>>();
    nms_reduce_kernel<<<BATCH, C_NT>>>(out);
}

// round 14
// speedup vs baseline: 2.1530x; 1.0349x over previous
#include <cuda_runtime.h>
#include <cuda_bf16.h>
#include <cstdint>

#define IMG_N_ANC   8649      // 31*31*9
#define PRE_NMS     6000
#define POST_NMS    1500
#define IOU_THR     0.7f
#define BATCH       16
#define NW          94        // 94 u64 words cover 6016 >= 6000 cols
#define NWP         96        // padded row stride (768 B)
#define NPAD        6016
#define NBIN        2048
#define NKEY        8704      // padded key capacity (>= 8649)

typedef unsigned long long u64;

// ---------------- device scratch (static; no allocations) ----------------
__device__ u64   g_masks[BATCH][NPAD][NWP];   // [b][row][word], ~73.9 MB
__device__ float g_y1[BATCH][NPAD];
__device__ float g_x1[BATCH][NPAD];
__device__ float g_y2[BATCH][NPAD];
__device__ float g_x2[BATCH][NPAD];
__device__ float g_ar[BATCH][NPAD];
__device__ float g_cs[BATCH][NPAD];           // ar * (0.7/1.7)
__device__ float g_sc[BATCH][NPAD];

// ================= Kernel A: bucket sort + decode top-6000 =================
#define A_NT          1024
#define A_OFF_RAW     0
#define A_OFF_SORT    (NKEY * 8)
#define A_OFF_HIST    (A_OFF_SORT + NKEY * 8)
#define A_OFF_START   (A_OFF_HIST + NBIN * 4)
#define A_SMEM_TOTAL  (A_OFF_START + NBIN * 4)

__global__ __launch_bounds__(A_NT, 1)
void sort_decode_kernel(const float* __restrict__ deltas,
                        const float* __restrict__ probs,
                        const float* __restrict__ anchors)
{
    extern __shared__ char smem[];
    u64* keys_raw    = (u64*)(smem + A_OFF_RAW);
    u64* keys_sorted = (u64*)(smem + A_OFF_SORT);
    unsigned int* hist  = (unsigned int*)(smem + A_OFF_HIST);
    unsigned int* start = (unsigned int*)(smem + A_OFF_START);

    const int b   = blockIdx.x;
    const int tid = threadIdx.x;
    const int nt  = A_NT;

    for (int i = tid; i < NBIN; i += nt) hist[i] = 0u;
    __syncthreads();

    const float* pb = probs + (size_t)b * IMG_N_ANC;
    for (int i = tid; i < IMG_N_ANC; i += nt) {
        float s = pb[i];
        unsigned int bits = __float_as_uint(s);
        u64 k = ((u64)bits << 32) | (u64)(0xFFFFFFFFu - (unsigned)i);
        keys_raw[i] = k;
        int bin = (int)(s * (float)NBIN);
        bin = max(0, min(NBIN - 1, bin));
        atomicAdd(&hist[bin], 1u);
    }
    __syncthreads();

    if (tid < 32) {
        const int lane = tid;
        int part = 0;
        #pragma unroll 8
        for (int q = 0; q < 64; q++) part += (int)hist[NBIN - 1 - (lane * 64 + q)];
        int inc = part;
        #pragma unroll
        for (int off = 1; off < 32; off <<= 1) {
            int v = __shfl_up_sync(0xFFFFFFFFu, inc, off);
            if (lane >= off) inc += v;
        }
        int excl = inc - part;
        for (int q = 0; q < 64; q++) {
            int v = NBIN - 1 - (lane * 64 + q);
            start[v] = (unsigned int)excl;
            excl += (int)hist[v];
        }
    }
    __syncthreads();

    for (int i = tid; i < NBIN; i += nt) hist[i] = 0u;
    __syncthreads();

    for (int i = tid; i < IMG_N_ANC; i += nt) {
        u64 k = keys_raw[i];
        float s = __uint_as_float((unsigned int)(k >> 32));
        int bin = (int)(s * (float)NBIN);
        bin = max(0, min(NBIN - 1, bin));
        unsigned int pos = start[bin] + atomicAdd(&hist[bin], 1u);
        keys_sorted[pos] = k;
    }
    __syncthreads();

    for (int v = tid; v < NBIN; v += nt) {
        int s0 = (int)start[v];
        int c  = (int)hist[v];
        if (s0 < PRE_NMS && c > 1) {
            for (int a = s0 + 1; a < s0 + c; a++) {
                u64 key = keys_sorted[a];
                int p = a - 1;
                while (p >= s0 && keys_sorted[p] < key) {
                    keys_sorted[p + 1] = keys_sorted[p];
                    p--;
                }
                keys_sorted[p + 1] = key;
            }
        }
    }
    __syncthreads();

    const float* db = deltas + (size_t)b * IMG_N_ANC * 4;
    for (int t = tid; t < PRE_NMS; t += nt) {
        u64 key = keys_sorted[t];
        unsigned int idx = 0xFFFFFFFFu - (unsigned int)(key & 0xFFFFFFFFull);
        float score = __uint_as_float((unsigned int)(key >> 32));

        float a0 = anchors[idx * 4 + 0];
        float a1 = anchors[idx * 4 + 1];
        float a2 = anchors[idx * 4 + 2];
        float a3 = anchors[idx * 4 + 3];
        float d0 = db[(size_t)idx * 4 + 0] * 0.1f;
        float d1 = db[(size_t)idx * 4 + 1] * 0.1f;
        float d2 = db[(size_t)idx * 4 + 2] * 0.2f;
        float d3 = db[(size_t)idx * 4 + 3] * 0.2f;

        float anc_h = a2 - a0;
        float anc_w = a3 - a1;
        float ctr_y = a0 + 0.5f * anc_h;
        float ctr_x = a1 + 0.5f * anc_w;
        float bh = expf(d2) * anc_h;
        float bw = expf(d3) * anc_w;
        float bcy = d0 * anc_h + ctr_y;
        float bcx = d1 * anc_w + ctr_x;
        float y1 = bcy - 0.5f * bh;
        float x1 = bcx - 0.5f * bw;
        float y2 = y1 + bh;
        float x2 = x1 + bw;

        float ar = (y2 - y1) * (x2 - x1);
        g_y1[b][t] = y1; g_x1[b][t] = x1;
        g_y2[b][t] = y2; g_x2[b][t] = x2;
        g_ar[b][t] = ar;
        g_cs[b][t] = ar * (IOU_THR / (1.0f + IOU_THR));
        g_sc[b][t] = score;
    }
}

// ================= Kernel B: forward suppression bit-matrix =================
// R13 geometry (1152 triangle blocks/batch, 64 thr, 4 rows/thread).
// NEW: per-pair band accumulation replaced by tmin aggregation.
//   tmin[r] = min over cols of (|diff| - (4e-6*ssum + 2e-8))
// tmin > 0  -> no pair of this row-word is within the fast/exact disagreement
// bound (<= ~8e-7*ssum + 0.41e-8, 5x margin) -> fast bits are exact.
// tmin <= 0 (rare, ~5e-4/row-word) -> re-scan the 64 cols and resolve the
// in-band ones with the exact reference chain.
#define B_BLOCKS 1152
#define B_RELB   4e-6f
#define B_ABSB   2e-8f

__device__ __forceinline__ bool iou_exact_hit(float ry1, float rx1, float ry2,
                                              float rx2, float rar,
                                              float4 c4, float ca)
{
    float ih = fmaxf(fminf(ry2, c4.z) - fmaxf(ry1, c4.x), 0.0f);
    float iw = fmaxf(fminf(rx2, c4.w) - fmaxf(rx1, c4.y), 0.0f);
    float inter = __fmul_rn(ih, iw);
    float dd = __fadd_rn(__fadd_rn(__fadd_rn(rar, ca), -inter), 1e-8f);
    return __fdiv_rn(inter, dd) > IOU_THR;
}

__global__ __launch_bounds__(64)
void iou_matrix_kernel()
{
    // decode linear block id -> (rb, cb) with cb >= 4*rb
    int t = blockIdx.x;
    int rb = 0;
    while (t >= 94 - 4 * rb) { t -= 94 - 4 * rb; rb++; }
    const int cb = 4 * rb + t;
    const int b   = blockIdx.y;
    const int tid = threadIdx.x;

    __shared__ float4 cbox[64];
    __shared__ float  cncs[64];
    __shared__ float  care[64];

    const int j0 = cb * 64;
    {
        int j = j0 + tid;
        if (j < PRE_NMS) {
            cbox[tid] = make_float4(g_y1[b][j], g_x1[b][j], g_y2[b][j], g_x2[b][j]);
            cncs[tid] = -g_cs[b][j];
            care[tid] = g_ar[b][j];
        } else {
            cbox[tid] = make_float4(0.f, 0.f, 0.f, 0.f);
            cncs[tid] = 0.f;
            care[tid] = 0.f;
        }
    }
    __syncthreads();

    float ry1[4], rx1[4], ry2[4], rx2[4], rncs[4], rar[4];
    #pragma unroll
    for (int r = 0; r < 4; r++) {
        int i = rb * 256 + r * 64 + tid;
        int ii = (i < PRE_NMS) ? i : 0;
        ry1[r] = g_y1[b][ii]; rx1[r] = g_x1[b][ii];
        ry2[r] = g_y2[b][ii]; rx2[r] = g_x2[b][ii];
        rncs[r] = -g_cs[b][ii]; rar[r] = g_ar[b][ii];
    }

    unsigned int bhi[4] = {0,0,0,0}, blo[4] = {0,0,0,0};
    float tmin[4] = {1e30f, 1e30f, 1e30f, 1e30f};

    #pragma unroll 8
    for (int j = 63; j >= 32; j--) {
        float4 c4 = cbox[j];
        float ncc = cncs[j];
        #pragma unroll
        for (int r = 0; r < 4; r++) {
            float ih = fmaxf(fminf(ry2[r], c4.z) - fmaxf(ry1[r], c4.x), 0.0f);
            float iw = fminf(rx2[r], c4.w) - fmaxf(rx1[r], c4.y);   // no 0-clamp
            float nss  = rncs[r] + ncc;
            float diff = fmaf(ih, iw, nss);
            float nthr = fmaf(B_RELB, nss, -B_ABSB);
            tmin[r] = fminf(tmin[r], fabsf(diff) + nthr);
            bhi[r] = bhi[r] * 2u + (unsigned)(diff > 0.0f);
        }
    }
    #pragma unroll 8
    for (int j = 31; j >= 0; j--) {
        float4 c4 = cbox[j];
        float ncc = cncs[j];
        #pragma unroll
        for (int r = 0; r < 4; r++) {
            float ih = fmaxf(fminf(ry2[r], c4.z) - fmaxf(ry1[r], c4.x), 0.0f);
            float iw = fminf(rx2[r], c4.w) - fmaxf(rx1[r], c4.y);   // no 0-clamp
            float nss  = rncs[r] + ncc;
            float diff = fmaf(ih, iw, nss);
            float nthr = fmaf(B_RELB, nss, -B_ABSB);
            tmin[r] = fminf(tmin[r], fabsf(diff) + nthr);
            blo[r] = blo[r] * 2u + (unsigned)(diff > 0.0f);
        }
    }

    // rare: some pair of this row-word is within the disagreement band —
    // re-scan and resolve in-band columns with the exact reference chain.
    #pragma unroll
    for (int r = 0; r < 4; r++) {
        if (tmin[r] <= 0.0f) {
            for (int j = 0; j < 64; j++) {
                float4 c4 = cbox[j];
                float ncc = cncs[j];
                float ih = fmaxf(fminf(ry2[r], c4.z) - fmaxf(ry1[r], c4.x), 0.0f);
                float iw = fminf(rx2[r], c4.w) - fmaxf(rx1[r], c4.y);
                float nss  = rncs[r] + ncc;
                float diff = fmaf(ih, iw, nss);
                float nthr = fmaf(B_RELB, nss, -B_ABSB);
                if (fabsf(diff) + nthr <= 0.0f) {
                    bool hit = iou_exact_hit(ry1[r], rx1[r], ry2[r], rx2[r],
                                             rar[r], c4, care[j]);
                    if (j < 32)
                        blo[r] = hit ? (blo[r] | (1u << j)) : (blo[r] & ~(1u << j));
                    else
                        bhi[r] = hit ? (bhi[r] | (1u << (j - 32)))
                                     : (bhi[r] & ~(1u << (j - 32)));
                }
            }
        }
    }

    #pragma unroll
    for (int r = 0; r < 4; r++) {
        int i = rb * 256 + r * 64 + tid;
        if (i < PRE_NMS && cb >= (i >> 6)) {
            u64 bits = ((u64)bhi[r] << 32) | (u64)blo[r];
            int dlt = i - j0;
            u64 m = (dlt < 0) ? ~0ull : ((dlt >= 63) ? 0ull : (~0ull << (dlt + 1)));
            g_masks[b][i][cb] = bits & m;
        }
    }
}

// ================= Kernel C: greedy bit-reduce + output ====================
// R13 version (proven): deferred owner ORs + publisher speculation.
#define C_NT 512
#define DEFN 12

__global__ __launch_bounds__(C_NT, 1)
void nms_reduce_kernel(float* __restrict__ out)
{
    const int b   = blockIdx.x;
    const int tid = threadIdx.x;

    __shared__ u64 s_diag[64];
    __shared__ u64 s_pub[4];
    __shared__ u64 s_keptmask;
    __shared__ int s_rows[64];
    __shared__ int s_nk;

    float* ob = out + (size_t)b * POST_NMS * 4;
    float* os = out + (size_t)BATCH * POST_NMS * 4 + (size_t)b * POST_NMS;

    for (int t = tid; t < POST_NMS * 4; t += C_NT) ob[t] = 0.0f;
    for (int t = tid; t < POST_NMS; t += C_NT)     os[t] = 0.0f;

    const int w   = tid >> 2;        // owned word (valid when tid < 376)
    const int sub = tid & 3;
    u64 rem = 0ull;
    u64 def[DEFN];
    #pragma unroll
    for (int q = 0; q < DEFN; q++) def[q] = 0ull;

    if (tid >= 448) s_diag[tid - 448] = g_masks[b][tid - 448][0];
    if (tid < 4) s_pub[tid] = 0ull;
    __syncthreads();

    int cnt = 0;
    for (int c = 0; c < NW; c++) {
        u64 remc = s_pub[0] | s_pub[1] | s_pub[2] | s_pub[3];
        int lim = PRE_NMS - c * 64;
        u64 alive = ~remc;
        if (lim < 64) alive &= ((1ull << lim) - 1ull);

        // consume deferred loads issued last chunk
        if (tid < 376 && w > c) {
            #pragma unroll
            for (int q = 0; q < DEFN; q++) rem |= def[q];
            #pragma unroll
            for (int q = 0; q < DEFN; q++) def[q] = 0ull;
        }

        // publisher speculation: 4 threads (w == c+1) cover ALL alive rows
        const bool is_pub = (tid < 376) && (w == c + 1);
        u64 spec[16];
        int specbit[16];
        if (is_pub) {
            u64 aa = alive;
            for (int k = 0; k < sub; k++) aa &= aa - 1ull;
            #pragma unroll
            for (int q = 0; q < 16; q++) {
                int bit = aa ? (__ffsll((long long)aa) - 1) : -1;
                specbit[q] = bit;
                spec[q] = (bit >= 0) ? g_masks[b][c * 64 + bit][w] : 0ull;
                aa &= aa - 1ull; aa &= aa - 1ull;
                aa &= aa - 1ull; aa &= aa - 1ull;
            }
        }

        // serial resolve (tid0)
        if (tid == 0) {
            u64 av = alive;
            u64 kept = 0ull;
            int nk = 0, cc = cnt;
            while (av && cc < POST_NMS) {
                int i = __ffsll((long long)av) - 1;
                s_rows[nk++] = c * 64 + i;
                kept |= (1ull << i);
                cc++;
                av &= ~(s_diag[i] | (1ull << i));
            }
            s_nk = nk;
            s_keptmask = kept;
        }
        __syncthreads();
        const int nk = s_nk;
        const u64 kept = s_keptmask;

        if (tid < nk) {
            int r    = s_rows[tid];
            int rank = cnt + tid;
            ob[rank * 4 + 0] = fminf(fmaxf(g_y1[b][r], 0.0f), 1.0f);
            ob[rank * 4 + 1] = fminf(fmaxf(g_x1[b][r], 0.0f), 1.0f);
            ob[rank * 4 + 2] = fminf(fmaxf(g_y2[b][r], 0.0f), 1.0f);
            ob[rank * 4 + 3] = fminf(fmaxf(g_x2[b][r], 0.0f), 1.0f);
            os[rank] = g_sc[b][r];
        }

        // non-publisher owners: ISSUE deferred loads (consume next chunk)
        if (tid < 376 && w > c + 1) {
            #pragma unroll
            for (int q = 0; q < DEFN; q++) {
                int m = sub + q * 4;
                bool v = (m < nk);
                int mm = v ? m : 0;
                def[q] = v ? g_masks[b][s_rows[mm]][w] : 0ull;
            }
            for (int m = sub + DEFN * 4; m < nk; m += 4)
                rem |= g_masks[b][s_rows[m]][w];
        }

        // publisher: OR kept spec entries, then publish next chunk's word
        if (is_pub) {
            #pragma unroll
            for (int q = 0; q < 16; q++) {
                if (specbit[q] >= 0 && ((kept >> specbit[q]) & 1ull))
                    rem |= spec[q];
            }
            s_pub[sub] = rem;
        }

        // prefetch next chunk's diagonal words
        if (c + 1 < NW && tid >= 448) {
            int row = (c + 1) * 64 + (tid - 448);
            s_diag[tid - 448] = (row < PRE_NMS) ? g_masks[b][row][c + 1] : 0ull;
        }

        cnt += nk;
        __syncthreads();
        if (cnt >= POST_NMS) break;
    }
}

// ============================== launch =====================================
extern "C" void kernel_launch(void* const* d_in, const int* in_sizes, int n_in,
                              void* d_out, int out_size) {
    const float* deltas  = (const float*)d_in[0];
    const float* probs   = (const float*)d_in[1];
    const float* anchors = (const float*)d_in[2];
    float* out = (float*)d_out;

    cudaFuncSetAttribute(sort_decode_kernel,
                         cudaFuncAttributeMaxDynamicSharedMemorySize, A_SMEM_TOTAL);

    sort_decode_kernel<<<BATCH, A_NT, A_SMEM_TOTAL>>>(deltas, probs, anchors);
    iou_matrix_kernel<<<dim3(B_BLOCKS, BATCH), 64>>>();
    nms_reduce_kernel<<<BATCH, C_NT>>>(out);
}

// round 15
// speedup vs baseline: 2.3040x; 1.0702x over previous
#include <cuda_runtime.h>
#include <cuda_bf16.h>
#include <cstdint>

#define IMG_N_ANC   8649      // 31*31*9
#define PRE_NMS     6000
#define POST_NMS    1500
#define IOU_THR     0.7f
#define BATCH       16
#define NW          94        // 94 u64 words cover 6016 >= 6000 cols
#define NWP         96        // padded row stride (768 B)
#define NPAD        6016
#define NBIN        2048
#define NKEY        8704      // padded key capacity (>= 8649)

typedef unsigned long long u64;

// ---------------- device scratch (static; no allocations) ----------------
__device__ u64   g_masks[BATCH][NPAD][NWP];   // [b][row][word], ~73.9 MB
__device__ float g_y1[BATCH][NPAD];
__device__ float g_x1[BATCH][NPAD];
__device__ float g_y2[BATCH][NPAD];
__device__ float g_x2[BATCH][NPAD];
__device__ float g_ar[BATCH][NPAD];
__device__ float g_cs[BATCH][NPAD];           // ar * (0.7/1.7)
__device__ float g_sc[BATCH][NPAD];

// ================= Kernel A: bucket sort + decode top-6000 =================
#define A_NT          1024
#define A_OFF_RAW     0
#define A_OFF_SORT    (NKEY * 8)
#define A_OFF_HIST    (A_OFF_SORT + NKEY * 8)
#define A_OFF_START   (A_OFF_HIST + NBIN * 4)
#define A_SMEM_TOTAL  (A_OFF_START + NBIN * 4)

__global__ __launch_bounds__(A_NT, 1)
void sort_decode_kernel(const float* __restrict__ deltas,
                        const float* __restrict__ probs,
                        const float* __restrict__ anchors)
{
    extern __shared__ char smem[];
    u64* keys_raw    = (u64*)(smem + A_OFF_RAW);
    u64* keys_sorted = (u64*)(smem + A_OFF_SORT);
    unsigned int* hist  = (unsigned int*)(smem + A_OFF_HIST);
    unsigned int* start = (unsigned int*)(smem + A_OFF_START);

    const int b   = blockIdx.x;
    const int tid = threadIdx.x;
    const int nt  = A_NT;

    for (int i = tid; i < NBIN; i += nt) hist[i] = 0u;
    __syncthreads();

    const float* pb = probs + (size_t)b * IMG_N_ANC;
    for (int i = tid; i < IMG_N_ANC; i += nt) {
        float s = pb[i];
        unsigned int bits = __float_as_uint(s);
        u64 k = ((u64)bits << 32) | (u64)(0xFFFFFFFFu - (unsigned)i);
        keys_raw[i] = k;
        int bin = (int)(s * (float)NBIN);
        bin = max(0, min(NBIN - 1, bin));
        atomicAdd(&hist[bin], 1u);
    }
    __syncthreads();

    if (tid < 32) {
        const int lane = tid;
        int part = 0;
        #pragma unroll 8
        for (int q = 0; q < 64; q++) part += (int)hist[NBIN - 1 - (lane * 64 + q)];
        int inc = part;
        #pragma unroll
        for (int off = 1; off < 32; off <<= 1) {
            int v = __shfl_up_sync(0xFFFFFFFFu, inc, off);
            if (lane >= off) inc += v;
        }
        int excl = inc - part;
        for (int q = 0; q < 64; q++) {
            int v = NBIN - 1 - (lane * 64 + q);
            start[v] = (unsigned int)excl;
            excl += (int)hist[v];
        }
    }
    __syncthreads();

    for (int i = tid; i < NBIN; i += nt) hist[i] = 0u;
    __syncthreads();

    for (int i = tid; i < IMG_N_ANC; i += nt) {
        u64 k = keys_raw[i];
        float s = __uint_as_float((unsigned int)(k >> 32));
        int bin = (int)(s * (float)NBIN);
        bin = max(0, min(NBIN - 1, bin));
        unsigned int pos = start[bin] + atomicAdd(&hist[bin], 1u);
        keys_sorted[pos] = k;
    }
    __syncthreads();

    for (int v = tid; v < NBIN; v += nt) {
        int s0 = (int)start[v];
        int c  = (int)hist[v];
        if (s0 < PRE_NMS && c > 1) {
            for (int a = s0 + 1; a < s0 + c; a++) {
                u64 key = keys_sorted[a];
                int p = a - 1;
                while (p >= s0 && keys_sorted[p] < key) {
                    keys_sorted[p + 1] = keys_sorted[p];
                    p--;
                }
                keys_sorted[p + 1] = key;
            }
        }
    }
    __syncthreads();

    const float* db = deltas + (size_t)b * IMG_N_ANC * 4;
    for (int t = tid; t < PRE_NMS; t += nt) {
        u64 key = keys_sorted[t];
        unsigned int idx = 0xFFFFFFFFu - (unsigned int)(key & 0xFFFFFFFFull);
        float score = __uint_as_float((unsigned int)(key >> 32));

        float a0 = anchors[idx * 4 + 0];
        float a1 = anchors[idx * 4 + 1];
        float a2 = anchors[idx * 4 + 2];
        float a3 = anchors[idx * 4 + 3];
        float d0 = db[(size_t)idx * 4 + 0] * 0.1f;
        float d1 = db[(size_t)idx * 4 + 1] * 0.1f;
        float d2 = db[(size_t)idx * 4 + 2] * 0.2f;
        float d3 = db[(size_t)idx * 4 + 3] * 0.2f;

        float anc_h = a2 - a0;
        float anc_w = a3 - a1;
        float ctr_y = a0 + 0.5f * anc_h;
        float ctr_x = a1 + 0.5f * anc_w;
        float bh = expf(d2) * anc_h;
        float bw = expf(d3) * anc_w;
        float bcy = d0 * anc_h + ctr_y;
        float bcx = d1 * anc_w + ctr_x;
        float y1 = bcy - 0.5f * bh;
        float x1 = bcx - 0.5f * bw;
        float y2 = y1 + bh;
        float x2 = x1 + bw;

        float ar = (y2 - y1) * (x2 - x1);
        g_y1[b][t] = y1; g_x1[b][t] = x1;
        g_y2[b][t] = y2; g_x2[b][t] = x2;
        g_ar[b][t] = ar;
        g_cs[b][t] = ar * (IOU_THR / (1.0f + IOU_THR));
        g_sc[b][t] = score;
    }
}

// ================= Kernel B: forward suppression bit-matrix =================
// R14 geometry (1152 triangle blocks/batch, 64 thr, 4 rows/thread).
// NEW per-pair core (decision-exact):
//   acc  = funnelshift(sign(diff))     -- 1 SHF replaces FSETP+SEL+IMAD
//   dmin = min(dmin, |diff|)           -- band threshold hoisted per row-word
// bits = ~acc. Row-words with dmin <= B_RELB*(rcs+csmax_tile)+B_ABSB rescan
// and resolve in-band columns (incl. diff==+-0 sign ambiguity) with the exact
// reference chain.
#define B_BLOCKS 1152
#define B_RELB   4e-6f
#define B_ABSB   2e-8f

__device__ __forceinline__ bool iou_exact_hit(float ry1, float rx1, float ry2,
                                              float rx2, float rar,
                                              float4 c4, float ca)
{
    float ih = fmaxf(fminf(ry2, c4.z) - fmaxf(ry1, c4.x), 0.0f);
    float iw = fmaxf(fminf(rx2, c4.w) - fmaxf(rx1, c4.y), 0.0f);
    float inter = __fmul_rn(ih, iw);
    float dd = __fadd_rn(__fadd_rn(__fadd_rn(rar, ca), -inter), 1e-8f);
    return __fdiv_rn(inter, dd) > IOU_THR;
}

__global__ __launch_bounds__(64)
void iou_matrix_kernel()
{
    // decode linear block id -> (rb, cb) with cb >= 4*rb
    int t = blockIdx.x;
    int rb = 0;
    while (t >= 94 - 4 * rb) { t -= 94 - 4 * rb; rb++; }
    const int cb = 4 * rb + t;
    const int b   = blockIdx.y;
    const int tid = threadIdx.x;

    __shared__ float4 cbox[64];
    __shared__ float  cncs[64];
    __shared__ float  care[64];
    __shared__ float  s_cnmin[2];

    const int j0 = cb * 64;
    float myncs;
    {
        int j = j0 + tid;
        if (j < PRE_NMS) {
            cbox[tid] = make_float4(g_y1[b][j], g_x1[b][j], g_y2[b][j], g_x2[b][j]);
            myncs = -g_cs[b][j];
            care[tid] = g_ar[b][j];
        } else {
            cbox[tid] = make_float4(0.f, 0.f, 0.f, 0.f);
            myncs = 0.f;
            care[tid] = 0.f;
        }
        cncs[tid] = myncs;
    }
    // per-tile min of cncs (== -max column cs) via warp butterfly
    {
        float v = myncs;
        #pragma unroll
        for (int off = 16; off > 0; off >>= 1)
            v = fminf(v, __shfl_xor_sync(0xFFFFFFFFu, v, off));
        if ((tid & 31) == 0) s_cnmin[tid >> 5] = v;
    }
    __syncthreads();
    const float cnmin = fminf(s_cnmin[0], s_cnmin[1]);

    float ry1[4], rx1[4], ry2[4], rx2[4], rncs[4], rar[4];
    #pragma unroll
    for (int r = 0; r < 4; r++) {
        int i = rb * 256 + r * 64 + tid;
        int ii = (i < PRE_NMS) ? i : 0;
        ry1[r] = g_y1[b][ii]; rx1[r] = g_x1[b][ii];
        ry2[r] = g_y2[b][ii]; rx2[r] = g_x2[b][ii];
        rncs[r] = -g_cs[b][ii]; rar[r] = g_ar[b][ii];
    }

    unsigned int ahi[4] = {0,0,0,0}, alo[4] = {0,0,0,0};
    float dmin[4] = {1e30f, 1e30f, 1e30f, 1e30f};

    #pragma unroll 8
    for (int j = 63; j >= 32; j--) {
        float4 c4 = cbox[j];
        float ncc = cncs[j];
        #pragma unroll
        for (int r = 0; r < 4; r++) {
            float ih = fmaxf(fminf(ry2[r], c4.z) - fmaxf(ry1[r], c4.x), 0.0f);
            float iw = fminf(rx2[r], c4.w) - fmaxf(rx1[r], c4.y);   // no 0-clamp
            float nss  = rncs[r] + ncc;
            float diff = fmaf(ih, iw, nss);
            dmin[r] = fminf(dmin[r], fabsf(diff));
            ahi[r] = __funnelshift_l(__float_as_uint(diff), ahi[r], 1);
        }
    }
    #pragma unroll 8
    for (int j = 31; j >= 0; j--) {
        float4 c4 = cbox[j];
        float ncc = cncs[j];
        #pragma unroll
        for (int r = 0; r < 4; r++) {
            float ih = fmaxf(fminf(ry2[r], c4.z) - fmaxf(ry1[r], c4.x), 0.0f);
            float iw = fminf(rx2[r], c4.w) - fmaxf(rx1[r], c4.y);   // no 0-clamp
            float nss  = rncs[r] + ncc;
            float diff = fmaf(ih, iw, nss);
            dmin[r] = fminf(dmin[r], fabsf(diff));
            alo[r] = __funnelshift_l(__float_as_uint(diff), alo[r], 1);
        }
    }

    unsigned int bhi[4], blo[4];
    #pragma unroll
    for (int r = 0; r < 4; r++) { bhi[r] = ~ahi[r]; blo[r] = ~alo[r]; }

    // rare: some pair of this row-word may be within the disagreement band —
    // re-scan and resolve in-band columns with the exact reference chain.
    #pragma unroll
    for (int r = 0; r < 4; r++) {
        float thr = fmaf(B_RELB, -(rncs[r] + cnmin), B_ABSB);  // rcs+csmax bound
        if (dmin[r] <= thr) {
            for (int j = 0; j < 64; j++) {
                float4 c4 = cbox[j];
                float ncc = cncs[j];
                float ih = fmaxf(fminf(ry2[r], c4.z) - fmaxf(ry1[r], c4.x), 0.0f);
                float iw = fminf(rx2[r], c4.w) - fmaxf(rx1[r], c4.y);
                float nss  = rncs[r] + ncc;
                float diff = fmaf(ih, iw, nss);
                float nthr = fmaf(B_RELB, nss, -B_ABSB);
                if (fabsf(diff) + nthr <= 0.0f) {
                    bool hit = iou_exact_hit(ry1[r], rx1[r], ry2[r], rx2[r],
                                             rar[r], c4, care[j]);
                    if (j < 32)
                        blo[r] = hit ? (blo[r] | (1u << j)) : (blo[r] & ~(1u << j));
                    else
                        bhi[r] = hit ? (bhi[r] | (1u << (j - 32)))
                                     : (bhi[r] & ~(1u << (j - 32)));
                }
            }
        }
    }

    #pragma unroll
    for (int r = 0; r < 4; r++) {
        int i = rb * 256 + r * 64 + tid;
        if (i < PRE_NMS && cb >= (i >> 6)) {
            u64 bits = ((u64)bhi[r] << 32) | (u64)blo[r];
            int dlt = i - j0;
            u64 m = (dlt < 0) ? ~0ull : ((dlt >= 63) ? 0ull : (~0ull << (dlt + 1)));
            g_masks[b][i][cb] = bits & m;
        }
    }
}

// ================= Kernel C: greedy bit-reduce + output ====================
// R13/R14 version (proven): deferred owner ORs + publisher speculation.
#define C_NT 512
#define DEFN 12

__global__ __launch_bounds__(C_NT, 1)
void nms_reduce_kernel(float* __restrict__ out)
{
    const int b   = blockIdx.x;
    const int tid = threadIdx.x;

    __shared__ u64 s_diag[64];
    __shared__ u64 s_pub[4];
    __shared__ u64 s_keptmask;
    __shared__ int s_rows[64];
    __shared__ int s_nk;

    float* ob = out + (size_t)b * POST_NMS * 4;
    float* os = out + (size_t)BATCH * POST_NMS * 4 + (size_t)b * POST_NMS;

    for (int t = tid; t < POST_NMS * 4; t += C_NT) ob[t] = 0.0f;
    for (int t = tid; t < POST_NMS; t += C_NT)     os[t] = 0.0f;

    const int w   = tid >> 2;        // owned word (valid when tid < 376)
    const int sub = tid & 3;
    u64 rem = 0ull;
    u64 def[DEFN];
    #pragma unroll
    for (int q = 0; q < DEFN; q++) def[q] = 0ull;

    if (tid >= 448) s_diag[tid - 448] = g_masks[b][tid - 448][0];
    if (tid < 4) s_pub[tid] = 0ull;
    __syncthreads();

    int cnt = 0;
    for (int c = 0; c < NW; c++) {
        u64 remc = s_pub[0] | s_pub[1] | s_pub[2] | s_pub[3];
        int lim = PRE_NMS - c * 64;
        u64 alive = ~remc;
        if (lim < 64) alive &= ((1ull << lim) - 1ull);

        // consume deferred loads issued last chunk
        if (tid < 376 && w > c) {
            #pragma unroll
            for (int q = 0; q < DEFN; q++) rem |= def[q];
            #pragma unroll
            for (int q = 0; q < DEFN; q++) def[q] = 0ull;
        }

        // publisher speculation: 4 threads (w == c+1) cover ALL alive rows
        const bool is_pub = (tid < 376) && (w == c + 1);
        u64 spec[16];
        int specbit[16];
        if (is_pub) {
            u64 aa = alive;
            for (int k = 0; k < sub; k++) aa &= aa - 1ull;
            #pragma unroll
            for (int q = 0; q < 16; q++) {
                int bit = aa ? (__ffsll((long long)aa) - 1) : -1;
                specbit[q] = bit;
                spec[q] = (bit >= 0) ? g_masks[b][c * 64 + bit][w] : 0ull;
                aa &= aa - 1ull; aa &= aa - 1ull;
                aa &= aa - 1ull; aa &= aa - 1ull;
            }
        }

        // serial resolve (tid0)
        if (tid == 0) {
            u64 av = alive;
            u64 kept = 0ull;
            int nk = 0, cc = cnt;
            while (av && cc < POST_NMS) {
                int i = __ffsll((long long)av) - 1;
                s_rows[nk++] = c * 64 + i;
                kept |= (1ull << i);
                cc++;
                av &= ~(s_diag[i] | (1ull << i));
            }
            s_nk = nk;
            s_keptmask = kept;
        }
        __syncthreads();
        const int nk = s_nk;
        const u64 kept = s_keptmask;

        if (tid < nk) {
            int r    = s_rows[tid];
            int rank = cnt + tid;
            ob[rank * 4 + 0] = fminf(fmaxf(g_y1[b][r], 0.0f), 1.0f);
            ob[rank * 4 + 1] = fminf(fmaxf(g_x1[b][r], 0.0f), 1.0f);
            ob[rank * 4 + 2] = fminf(fmaxf(g_y2[b][r], 0.0f), 1.0f);
            ob[rank * 4 + 3] = fminf(fmaxf(g_x2[b][r], 0.0f), 1.0f);
            os[rank] = g_sc[b][r];
        }

        // non-publisher owners: ISSUE deferred loads (consume next chunk)
        if (tid < 376 && w > c + 1) {
            #pragma unroll
            for (int q = 0; q < DEFN; q++) {
                int m = sub + q * 4;
                bool v = (m < nk);
                int mm = v ? m : 0;
                def[q] = v ? g_masks[b][s_rows[mm]][w] : 0ull;
            }
            for (int m = sub + DEFN * 4; m < nk; m += 4)
                rem |= g_masks[b][s_rows[m]][w];
        }

        // publisher: OR kept spec entries, then publish next chunk's word
        if (is_pub) {
            #pragma unroll
            for (int q = 0; q < 16; q++) {
                if (specbit[q] >= 0 && ((kept >> specbit[q]) & 1ull))
                    rem |= spec[q];
            }
            s_pub[sub] = rem;
        }

        // prefetch next chunk's diagonal words
        if (c + 1 < NW && tid >= 448) {
            int row = (c + 1) * 64 + (tid - 448);
            s_diag[tid - 448] = (row < PRE_NMS) ? g_masks[b][row][c + 1] : 0ull;
        }

        cnt += nk;
        __syncthreads();
        if (cnt >= POST_NMS) break;
    }
}

// ============================== launch =====================================
extern "C" void kernel_launch(void* const* d_in, const int* in_sizes, int n_in,
                              void* d_out, int out_size) {
    const float* deltas  = (const float*)d_in[0];
    const float* probs   = (const float*)d_in[1];
    const float* anchors = (const float*)d_in[2];
    float* out = (float*)d_out;

    cudaFuncSetAttribute(sort_decode_kernel,
                         cudaFuncAttributeMaxDynamicSharedMemorySize, A_SMEM_TOTAL);

    sort_decode_kernel<<<BATCH, A_NT, A_SMEM_TOTAL>>>(deltas, probs, anchors);
    iou_matrix_kernel<<<dim3(B_BLOCKS, BATCH), 64>>>();
    nms_reduce_kernel<<<BATCH, C_NT>>>(out);
}

// round 16
// speedup vs baseline: 2.3108x; 1.0029x over previous
#include <cuda_runtime.h>
#include <cuda_bf16.h>
#include <cstdint>

#define IMG_N_ANC   8649      // 31*31*9
#define PRE_NMS     6000
#define POST_NMS    1500
#define IOU_THR     0.7f
#define BATCH       16
#define NW          94        // 94 u64 words cover 6016 >= 6000 cols
#define NWP         96        // padded row stride (768 B)
#define NPAD        6016
#define NBIN        2048
#define NKEY        8704
#define HALF_W      47        // phase split: words 0..46 | 47..93
#define HALF_ROWS   3008      // = HALF_W * 64

typedef unsigned long long u64;

// ---------------- device scratch (static; no allocations) ----------------
__device__ u64   g_masks[BATCH][NPAD][NWP];   // [b][row][word]
__device__ float g_y1[BATCH][NPAD];
__device__ float g_x1[BATCH][NPAD];
__device__ float g_y2[BATCH][NPAD];
__device__ float g_x2[BATCH][NPAD];
__device__ float g_ar[BATCH][NPAD];
__device__ float g_cs[BATCH][NPAD];           // ar * (0.7/1.7)
__device__ float g_sc[BATCH][NPAD];
__device__ int   g_kept[BATCH][1536];         // kept rows from phase 1
__device__ int   g_kcnt[BATCH];

// ================= Kernel A: bucket sort + decode top-6000 =================
#define A_NT          1024
#define A_OFF_RAW     0
#define A_OFF_SORT    (NKEY * 8)
#define A_OFF_HIST    (A_OFF_SORT + NKEY * 8)
#define A_OFF_START   (A_OFF_HIST + NBIN * 4)
#define A_SMEM_TOTAL  (A_OFF_START + NBIN * 4)

__global__ __launch_bounds__(A_NT, 1)
void sort_decode_kernel(const float* __restrict__ deltas,
                        const float* __restrict__ probs,
                        const float* __restrict__ anchors)
{
    extern __shared__ char smem[];
    u64* keys_raw    = (u64*)(smem + A_OFF_RAW);
    u64* keys_sorted = (u64*)(smem + A_OFF_SORT);
    unsigned int* hist  = (unsigned int*)(smem + A_OFF_HIST);
    unsigned int* start = (unsigned int*)(smem + A_OFF_START);

    const int b   = blockIdx.x;
    const int tid = threadIdx.x;
    const int nt  = A_NT;

    for (int i = tid; i < NBIN; i += nt) hist[i] = 0u;
    __syncthreads();

    const float* pb = probs + (size_t)b * IMG_N_ANC;
    for (int i = tid; i < IMG_N_ANC; i += nt) {
        float s = pb[i];
        unsigned int bits = __float_as_uint(s);
        u64 k = ((u64)bits << 32) | (u64)(0xFFFFFFFFu - (unsigned)i);
        keys_raw[i] = k;
        int bin = (int)(s * (float)NBIN);
        bin = max(0, min(NBIN - 1, bin));
        atomicAdd(&hist[bin], 1u);
    }
    __syncthreads();

    if (tid < 32) {
        const int lane = tid;
        int part = 0;
        #pragma unroll 8
        for (int q = 0; q < 64; q++) part += (int)hist[NBIN - 1 - (lane * 64 + q)];
        int inc = part;
        #pragma unroll
        for (int off = 1; off < 32; off <<= 1) {
            int v = __shfl_up_sync(0xFFFFFFFFu, inc, off);
            if (lane >= off) inc += v;
        }
        int excl = inc - part;
        for (int q = 0; q < 64; q++) {
            int v = NBIN - 1 - (lane * 64 + q);
            start[v] = (unsigned int)excl;
            excl += (int)hist[v];
        }
    }
    __syncthreads();

    for (int i = tid; i < NBIN; i += nt) hist[i] = 0u;
    __syncthreads();

    for (int i = tid; i < IMG_N_ANC; i += nt) {
        u64 k = keys_raw[i];
        float s = __uint_as_float((unsigned int)(k >> 32));
        int bin = (int)(s * (float)NBIN);
        bin = max(0, min(NBIN - 1, bin));
        unsigned int pos = start[bin] + atomicAdd(&hist[bin], 1u);
        keys_sorted[pos] = k;
    }
    __syncthreads();

    for (int v = tid; v < NBIN; v += nt) {
        int s0 = (int)start[v];
        int c  = (int)hist[v];
        if (s0 < PRE_NMS && c > 1) {
            for (int a = s0 + 1; a < s0 + c; a++) {
                u64 key = keys_sorted[a];
                int p = a - 1;
                while (p >= s0 && keys_sorted[p] < key) {
                    keys_sorted[p + 1] = keys_sorted[p];
                    p--;
                }
                keys_sorted[p + 1] = key;
            }
        }
    }
    __syncthreads();

    const float* db = deltas + (size_t)b * IMG_N_ANC * 4;
    for (int t = tid; t < PRE_NMS; t += nt) {
        u64 key = keys_sorted[t];
        unsigned int idx = 0xFFFFFFFFu - (unsigned int)(key & 0xFFFFFFFFull);
        float score = __uint_as_float((unsigned int)(key >> 32));

        float a0 = anchors[idx * 4 + 0];
        float a1 = anchors[idx * 4 + 1];
        float a2 = anchors[idx * 4 + 2];
        float a3 = anchors[idx * 4 + 3];
        float d0 = db[(size_t)idx * 4 + 0] * 0.1f;
        float d1 = db[(size_t)idx * 4 + 1] * 0.1f;
        float d2 = db[(size_t)idx * 4 + 2] * 0.2f;
        float d3 = db[(size_t)idx * 4 + 3] * 0.2f;

        float anc_h = a2 - a0;
        float anc_w = a3 - a1;
        float ctr_y = a0 + 0.5f * anc_h;
        float ctr_x = a1 + 0.5f * anc_w;
        float bh = expf(d2) * anc_h;
        float bw = expf(d3) * anc_w;
        float bcy = d0 * anc_h + ctr_y;
        float bcx = d1 * anc_w + ctr_x;
        float y1 = bcy - 0.5f * bh;
        float x1 = bcx - 0.5f * bw;
        float y2 = y1 + bh;
        float x2 = x1 + bw;

        float ar = (y2 - y1) * (x2 - x1);
        g_y1[b][t] = y1; g_x1[b][t] = x1;
        g_y2[b][t] = y2; g_x2[b][t] = x2;
        g_ar[b][t] = ar;
        g_cs[b][t] = ar * (IOU_THR / (1.0f + IOU_THR));
        g_sc[b][t] = score;
    }
}

// ===================== B core constants (proven R15) ========================
#define B_RELB   4e-6f
#define B_ABSB   2e-8f
#define B_TRI_BLOCKS 300   // sum over rb=0..11 of (47 - 4*rb)

__device__ __forceinline__ bool iou_exact_hit(float ry1, float rx1, float ry2,
                                              float rx2, float rar,
                                              float4 c4, float ca)
{
    float ih = fmaxf(fminf(ry2, c4.z) - fmaxf(ry1, c4.x), 0.0f);
    float iw = fmaxf(fminf(rx2, c4.w) - fmaxf(rx1, c4.y), 0.0f);
    float inter = __fmul_rn(ih, iw);
    float dd = __fadd_rn(__fadd_rn(__fadd_rn(rar, ca), -inter), 1e-8f);
    return __fdiv_rn(inter, dd) > IOU_THR;
}

// ============ Kernel B-tri: triangle half (rows x words of one phase) =======
// row_base/colw_base = (0,0) for phase 1, (3008,47) for phase 2 lower-right.
// grid (300, 16); decode t -> (rb, cb_local) with cb_local in [4rb, 47).
__global__ __launch_bounds__(64)
void iou_tri_kernel(int row_base, int colw_base)
{
    int t = blockIdx.x;
    int rb = 0;
    while (t >= 47 - 4 * rb) { t -= 47 - 4 * rb; rb++; }
    const int cb = colw_base + 4 * rb + t;
    const int b   = blockIdx.y;
    const int tid = threadIdx.x;

    __shared__ float4 cbox[64];
    __shared__ float  cncs[64];
    __shared__ float  care[64];
    __shared__ float  s_cnmin[2];

    const int j0 = cb * 64;
    float myncs;
    {
        int j = j0 + tid;
        if (j < PRE_NMS) {
            cbox[tid] = make_float4(g_y1[b][j], g_x1[b][j], g_y2[b][j], g_x2[b][j]);
            myncs = -g_cs[b][j];
            care[tid] = g_ar[b][j];
        } else {
            cbox[tid] = make_float4(0.f, 0.f, 0.f, 0.f);
            myncs = 0.f;
            care[tid] = 0.f;
        }
        cncs[tid] = myncs;
    }
    {
        float v = myncs;
        #pragma unroll
        for (int off = 16; off > 0; off >>= 1)
            v = fminf(v, __shfl_xor_sync(0xFFFFFFFFu, v, off));
        if ((tid & 31) == 0) s_cnmin[tid >> 5] = v;
    }
    __syncthreads();
    const float cnmin = fminf(s_cnmin[0], s_cnmin[1]);

    float ry1[4], rx1[4], ry2[4], rx2[4], rncs[4], rar[4];
    #pragma unroll
    for (int r = 0; r < 4; r++) {
        int i = row_base + rb * 256 + r * 64 + tid;
        int ii = (i < PRE_NMS) ? i : 0;
        ry1[r] = g_y1[b][ii]; rx1[r] = g_x1[b][ii];
        ry2[r] = g_y2[b][ii]; rx2[r] = g_x2[b][ii];
        rncs[r] = -g_cs[b][ii]; rar[r] = g_ar[b][ii];
    }

    unsigned int ahi[4] = {0,0,0,0}, alo[4] = {0,0,0,0};
    float dmin[4] = {1e30f, 1e30f, 1e30f, 1e30f};

    #pragma unroll 8
    for (int j = 63; j >= 32; j--) {
        float4 c4 = cbox[j];
        float ncc = cncs[j];
        #pragma unroll
        for (int r = 0; r < 4; r++) {
            float ih = fmaxf(fminf(ry2[r], c4.z) - fmaxf(ry1[r], c4.x), 0.0f);
            float iw = fminf(rx2[r], c4.w) - fmaxf(rx1[r], c4.y);
            float nss  = rncs[r] + ncc;
            float diff = fmaf(ih, iw, nss);
            dmin[r] = fminf(dmin[r], fabsf(diff));
            ahi[r] = __funnelshift_l(__float_as_uint(diff), ahi[r], 1);
        }
    }
    #pragma unroll 8
    for (int j = 31; j >= 0; j--) {
        float4 c4 = cbox[j];
        float ncc = cncs[j];
        #pragma unroll
        for (int r = 0; r < 4; r++) {
            float ih = fmaxf(fminf(ry2[r], c4.z) - fmaxf(ry1[r], c4.x), 0.0f);
            float iw = fminf(rx2[r], c4.w) - fmaxf(rx1[r], c4.y);
            float nss  = rncs[r] + ncc;
            float diff = fmaf(ih, iw, nss);
            dmin[r] = fminf(dmin[r], fabsf(diff));
            alo[r] = __funnelshift_l(__float_as_uint(diff), alo[r], 1);
        }
    }

    unsigned int bhi[4], blo[4];
    #pragma unroll
    for (int r = 0; r < 4; r++) { bhi[r] = ~ahi[r]; blo[r] = ~alo[r]; }

    #pragma unroll
    for (int r = 0; r < 4; r++) {
        float thr = fmaf(B_RELB, -(rncs[r] + cnmin), B_ABSB);
        if (dmin[r] <= thr) {
            for (int j = 0; j < 64; j++) {
                float4 c4 = cbox[j];
                float ncc = cncs[j];
                float ih = fmaxf(fminf(ry2[r], c4.z) - fmaxf(ry1[r], c4.x), 0.0f);
                float iw = fminf(rx2[r], c4.w) - fmaxf(rx1[r], c4.y);
                float nss  = rncs[r] + ncc;
                float diff = fmaf(ih, iw, nss);
                float nthr = fmaf(B_RELB, nss, -B_ABSB);
                if (fabsf(diff) + nthr <= 0.0f) {
                    bool hit = iou_exact_hit(ry1[r], rx1[r], ry2[r], rx2[r],
                                             rar[r], c4, care[j]);
                    if (j < 32)
                        blo[r] = hit ? (blo[r] | (1u << j)) : (blo[r] & ~(1u << j));
                    else
                        bhi[r] = hit ? (bhi[r] | (1u << (j - 32)))
                                     : (bhi[r] & ~(1u << (j - 32)));
                }
            }
        }
    }

    #pragma unroll
    for (int r = 0; r < 4; r++) {
        int i = row_base + rb * 256 + r * 64 + tid;
        if (i < PRE_NMS && cb >= (i >> 6)) {
            u64 bits = ((u64)bhi[r] << 32) | (u64)blo[r];
            int dlt = i - j0;
            u64 m = (dlt < 0) ? ~0ull : ((dlt >= 63) ? 0ull : (~0ull << (dlt + 1)));
            g_masks[b][i][cb] = bits & m;
        }
    }
}

// ====== Kernel B2a: kept phase-1 rows x phase-2 words =======================
// grid (47, 6, 16): cb = 47 + bx; kept slot m = by*256 + r*64 + tid.
// Rows < 3008 < all cols here, so masks are fully forward (no diag masking).
__global__ __launch_bounds__(64)
void iou_kept_kernel()
{
    const int cb  = HALF_W + blockIdx.x;
    const int b   = blockIdx.z;
    const int tid = threadIdx.x;
    const int kcnt = g_kcnt[b];
    if (blockIdx.y * 256 >= kcnt) return;

    __shared__ float4 cbox[64];
    __shared__ float  cncs[64];
    __shared__ float  care[64];
    __shared__ float  s_cnmin[2];

    const int j0 = cb * 64;
    float myncs;
    {
        int j = j0 + tid;
        if (j < PRE_NMS) {
            cbox[tid] = make_float4(g_y1[b][j], g_x1[b][j], g_y2[b][j], g_x2[b][j]);
            myncs = -g_cs[b][j];
            care[tid] = g_ar[b][j];
        } else {
            cbox[tid] = make_float4(0.f, 0.f, 0.f, 0.f);
            myncs = 0.f;
            care[tid] = 0.f;
        }
        cncs[tid] = myncs;
    }
    {
        float v = myncs;
        #pragma unroll
        for (int off = 16; off > 0; off >>= 1)
            v = fminf(v, __shfl_xor_sync(0xFFFFFFFFu, v, off));
        if ((tid & 31) == 0) s_cnmin[tid >> 5] = v;
    }
    __syncthreads();
    const float cnmin = fminf(s_cnmin[0], s_cnmin[1]);

    float ry1[4], rx1[4], ry2[4], rx2[4], rncs[4], rar[4];
    int   ri[4];
    bool  act[4];
    #pragma unroll
    for (int r = 0; r < 4; r++) {
        int m = blockIdx.y * 256 + r * 64 + tid;
        act[r] = (m < kcnt);
        int row = act[r] ? g_kept[b][m] : 0;
        ri[r] = row;
        ry1[r] = g_y1[b][row]; rx1[r] = g_x1[b][row];
        ry2[r] = g_y2[b][row]; rx2[r] = g_x2[b][row];
        rncs[r] = -g_cs[b][row]; rar[r] = g_ar[b][row];
    }

    unsigned int ahi[4] = {0,0,0,0}, alo[4] = {0,0,0,0};
    float dmin[4] = {1e30f, 1e30f, 1e30f, 1e30f};

    #pragma unroll 8
    for (int j = 63; j >= 32; j--) {
        float4 c4 = cbox[j];
        float ncc = cncs[j];
        #pragma unroll
        for (int r = 0; r < 4; r++) {
            float ih = fmaxf(fminf(ry2[r], c4.z) - fmaxf(ry1[r], c4.x), 0.0f);
            float iw = fminf(rx2[r], c4.w) - fmaxf(rx1[r], c4.y);
            float nss  = rncs[r] + ncc;
            float diff = fmaf(ih, iw, nss);
            dmin[r] = fminf(dmin[r], fabsf(diff));
            ahi[r] = __funnelshift_l(__float_as_uint(diff), ahi[r], 1);
        }
    }
    #pragma unroll 8
    for (int j = 31; j >= 0; j--) {
        float4 c4 = cbox[j];
        float ncc = cncs[j];
        #pragma unroll
        for (int r = 0; r < 4; r++) {
            float ih = fmaxf(fminf(ry2[r], c4.z) - fmaxf(ry1[r], c4.x), 0.0f);
            float iw = fminf(rx2[r], c4.w) - fmaxf(rx1[r], c4.y);
            float nss  = rncs[r] + ncc;
            float diff = fmaf(ih, iw, nss);
            dmin[r] = fminf(dmin[r], fabsf(diff));
            alo[r] = __funnelshift_l(__float_as_uint(diff), alo[r], 1);
        }
    }

    unsigned int bhi[4], blo[4];
    #pragma unroll
    for (int r = 0; r < 4; r++) { bhi[r] = ~ahi[r]; blo[r] = ~alo[r]; }

    #pragma unroll
    for (int r = 0; r < 4; r++) {
        float thr = fmaf(B_RELB, -(rncs[r] + cnmin), B_ABSB);
        if (act[r] && dmin[r] <= thr) {
            for (int j = 0; j < 64; j++) {
                float4 c4 = cbox[j];
                float ncc = cncs[j];
                float ih = fmaxf(fminf(ry2[r], c4.z) - fmaxf(ry1[r], c4.x), 0.0f);
                float iw = fminf(rx2[r], c4.w) - fmaxf(rx1[r], c4.y);
                float nss  = rncs[r] + ncc;
                float diff = fmaf(ih, iw, nss);
                float nthr = fmaf(B_RELB, nss, -B_ABSB);
                if (fabsf(diff) + nthr <= 0.0f) {
                    bool hit = iou_exact_hit(ry1[r], rx1[r], ry2[r], rx2[r],
                                             rar[r], c4, care[j]);
                    if (j < 32)
                        blo[r] = hit ? (blo[r] | (1u << j)) : (blo[r] & ~(1u << j));
                    else
                        bhi[r] = hit ? (bhi[r] | (1u << (j - 32)))
                                     : (bhi[r] & ~(1u << (j - 32)));
                }
            }
        }
    }

    #pragma unroll
    for (int r = 0; r < 4; r++) {
        if (act[r]) {
            u64 bits = ((u64)bhi[r] << 32) | (u64)blo[r];
            g_masks[b][ri[r]][cb] = bits;       // fully forward: no diag mask
        }
    }
}

// ================= Kernel C1: chunks 0..46, record kept rows ================
#define C_NT 512
#define DEFN 12

__global__ __launch_bounds__(C_NT, 1)
void nms_phase1_kernel(float* __restrict__ out)
{
    const int b   = blockIdx.x;
    const int tid = threadIdx.x;

    __shared__ u64 s_diag[64];
    __shared__ u64 s_pub[4];
    __shared__ u64 s_keptmask;
    __shared__ int s_rows[64];
    __shared__ int s_nk;

    float* ob = out + (size_t)b * POST_NMS * 4;
    float* os = out + (size_t)BATCH * POST_NMS * 4 + (size_t)b * POST_NMS;

    for (int t = tid; t < POST_NMS * 4; t += C_NT) ob[t] = 0.0f;
    for (int t = tid; t < POST_NMS; t += C_NT)     os[t] = 0.0f;

    const int w   = tid >> 2;
    const int sub = tid & 3;
    u64 rem = 0ull;
    u64 def[DEFN];
    #pragma unroll
    for (int q = 0; q < DEFN; q++) def[q] = 0ull;

    if (tid >= 448) s_diag[tid - 448] = g_masks[b][tid - 448][0];
    if (tid < 4) s_pub[tid] = 0ull;
    __syncthreads();

    int cnt = 0;
    for (int c = 0; c < HALF_W; c++) {
        u64 remc = s_pub[0] | s_pub[1] | s_pub[2] | s_pub[3];
        u64 alive = ~remc;      // lim always 64 for c < 47

        if (tid < 376 && w > c && w < HALF_W) {
            #pragma unroll
            for (int q = 0; q < DEFN; q++) rem |= def[q];
            #pragma unroll
            for (int q = 0; q < DEFN; q++) def[q] = 0ull;
        }

        const bool is_pub = (tid < 376) && (w == c + 1) && (c + 1 < HALF_W);
        u64 spec[16];
        int specbit[16];
        if (is_pub) {
            u64 aa = alive;
            for (int k = 0; k < sub; k++) aa &= aa - 1ull;
            #pragma unroll
            for (int q = 0; q < 16; q++) {
                int bit = aa ? (__ffsll((long long)aa) - 1) : -1;
                specbit[q] = bit;
                spec[q] = (bit >= 0) ? g_masks[b][c * 64 + bit][w] : 0ull;
                aa &= aa - 1ull; aa &= aa - 1ull;
                aa &= aa - 1ull; aa &= aa - 1ull;
            }
        }

        if (tid == 0) {
            u64 av = alive;
            u64 kept = 0ull;
            int nk = 0, cc = cnt;
            while (av && cc < POST_NMS) {
                int i = __ffsll((long long)av) - 1;
                s_rows[nk++] = c * 64 + i;
                kept |= (1ull << i);
                cc++;
                av &= ~(s_diag[i] | (1ull << i));
            }
            s_nk = nk;
            s_keptmask = kept;
        }
        __syncthreads();
        const int nk = s_nk;
        const u64 kept = s_keptmask;

        if (tid < nk) {
            int r    = s_rows[tid];
            int rank = cnt + tid;
            ob[rank * 4 + 0] = fminf(fmaxf(g_y1[b][r], 0.0f), 1.0f);
            ob[rank * 4 + 1] = fminf(fmaxf(g_x1[b][r], 0.0f), 1.0f);
            ob[rank * 4 + 2] = fminf(fmaxf(g_y2[b][r], 0.0f), 1.0f);
            ob[rank * 4 + 3] = fminf(fmaxf(g_x2[b][r], 0.0f), 1.0f);
            os[rank] = g_sc[b][r];
            g_kept[b][rank] = r;                 // record kept row
        }

        if (tid < 376 && w > c + 1 && w < HALF_W) {
            #pragma unroll
            for (int q = 0; q < DEFN; q++) {
                int m = sub + q * 4;
                bool v = (m < nk);
                int mm = v ? m : 0;
                def[q] = v ? g_masks[b][s_rows[mm]][w] : 0ull;
            }
            for (int m = sub + DEFN * 4; m < nk; m += 4)
                rem |= g_masks[b][s_rows[m]][w];
        }

        if (is_pub) {
            #pragma unroll
            for (int q = 0; q < 16; q++) {
                if (specbit[q] >= 0 && ((kept >> specbit[q]) & 1ull))
                    rem |= spec[q];
            }
            s_pub[sub] = rem;
        }

        if (c + 1 < HALF_W && tid >= 448) {
            int row = (c + 1) * 64 + (tid - 448);
            s_diag[tid - 448] = g_masks[b][row][c + 1];
        }

        cnt += nk;
        __syncthreads();
        if (cnt >= POST_NMS) break;
    }

    if (tid == 0) g_kcnt[b] = cnt;
}

// ================= Kernel C2: prologue OR + chunks 47..93 ===================
__global__ __launch_bounds__(C_NT, 1)
void nms_phase2_kernel(float* __restrict__ out)
{
    const int b   = blockIdx.x;
    const int tid = threadIdx.x;

    __shared__ u64 s_diag[64];
    __shared__ u64 s_pub[4];
    __shared__ u64 s_keptmask;
    __shared__ int s_rows[64];
    __shared__ int s_nk;

    float* ob = out + (size_t)b * POST_NMS * 4;
    float* os = out + (size_t)BATCH * POST_NMS * 4 + (size_t)b * POST_NMS;

    const int w   = tid >> 2;
    const int sub = tid & 3;
    const int kcnt = g_kcnt[b];
    u64 rem = 0ull;
    u64 def[DEFN];
    #pragma unroll
    for (int q = 0; q < DEFN; q++) def[q] = 0ull;

    // prologue: fold phase-1 kept rows' suppression into owner words >= 47
    if (tid < 376 && w >= HALF_W) {
        for (int m = sub; m < kcnt; m += 4)
            rem |= g_masks[b][g_kept[b][m]][w];
    }
    if (tid < 376 && w == HALF_W) s_pub[sub] = rem;
    if (tid >= 448) s_diag[tid - 448] = g_masks[b][HALF_W * 64 + (tid - 448)][HALF_W];
    __syncthreads();

    int cnt = kcnt;
    for (int c = HALF_W; c < NW; c++) {
        u64 remc = s_pub[0] | s_pub[1] | s_pub[2] | s_pub[3];
        int lim = PRE_NMS - c * 64;
        u64 alive = ~remc;
        if (lim < 64) alive &= ((1ull << lim) - 1ull);

        if (tid < 376 && w > c) {
            #pragma unroll
            for (int q = 0; q < DEFN; q++) rem |= def[q];
            #pragma unroll
            for (int q = 0; q < DEFN; q++) def[q] = 0ull;
        }

        const bool is_pub = (tid < 376) && (w == c + 1);
        u64 spec[16];
        int specbit[16];
        if (is_pub) {
            u64 aa = alive;
            for (int k = 0; k < sub; k++) aa &= aa - 1ull;
            #pragma unroll
            for (int q = 0; q < 16; q++) {
                int bit = aa ? (__ffsll((long long)aa) - 1) : -1;
                specbit[q] = bit;
                spec[q] = (bit >= 0) ? g_masks[b][c * 64 + bit][w] : 0ull;
                aa &= aa - 1ull; aa &= aa - 1ull;
                aa &= aa - 1ull; aa &= aa - 1ull;
            }
        }

        if (tid == 0) {
            u64 av = alive;
            u64 kept = 0ull;
            int nk = 0, cc = cnt;
            while (av && cc < POST_NMS) {
                int i = __ffsll((long long)av) - 1;
                s_rows[nk++] = c * 64 + i;
                kept |= (1ull << i);
                cc++;
                av &= ~(s_diag[i] | (1ull << i));
            }
            s_nk = nk;
            s_keptmask = kept;
        }
        __syncthreads();
        const int nk = s_nk;
        const u64 kept = s_keptmask;

        if (tid < nk) {
            int r    = s_rows[tid];
            int rank = cnt + tid;
            ob[rank * 4 + 0] = fminf(fmaxf(g_y1[b][r], 0.0f), 1.0f);
            ob[rank * 4 + 1] = fminf(fmaxf(g_x1[b][r], 0.0f), 1.0f);
            ob[rank * 4 + 2] = fminf(fmaxf(g_y2[b][r], 0.0f), 1.0f);
            ob[rank * 4 + 3] = fminf(fmaxf(g_x2[b][r], 0.0f), 1.0f);
            os[rank] = g_sc[b][r];
        }

        if (tid < 376 && w > c + 1) {
            #pragma unroll
            for (int q = 0; q < DEFN; q++) {
                int m = sub + q * 4;
                bool v = (m < nk);
                int mm = v ? m : 0;
                def[q] = v ? g_masks[b][s_rows[mm]][w] : 0ull;
            }
            for (int m = sub + DEFN * 4; m < nk; m += 4)
                rem |= g_masks[b][s_rows[m]][w];
        }

        if (is_pub) {
            #pragma unroll
            for (int q = 0; q < 16; q++) {
                if (specbit[q] >= 0 && ((kept >> specbit[q]) & 1ull))
                    rem |= spec[q];
            }
            s_pub[sub] = rem;
        }

        if (c + 1 < NW && tid >= 448) {
            int row = (c + 1) * 64 + (tid - 448);
            s_diag[tid - 448] = (row < PRE_NMS) ? g_masks[b][row][c + 1] : 0ull;
        }

        cnt += nk;
        __syncthreads();
        if (cnt >= POST_NMS) break;
    }
}

// ============================== launch =====================================
extern "C" void kernel_launch(void* const* d_in, const int* in_sizes, int n_in,
                              void* d_out, int out_size) {
    const float* deltas  = (const float*)d_in[0];
    const float* probs   = (const float*)d_in[1];
    const float* anchors = (const float*)d_in[2];
    float* out = (float*)d_out;

    cudaFuncSetAttribute(sort_decode_kernel,
                         cudaFuncAttributeMaxDynamicSharedMemorySize, A_SMEM_TOTAL);

    sort_decode_kernel<<<BATCH, A_NT, A_SMEM_TOTAL>>>(deltas, probs, anchors);
    iou_tri_kernel<<<dim3(B_TRI_BLOCKS, BATCH), 64>>>(0, 0);                 // B1
    iou_tri_kernel<<<dim3(B_TRI_BLOCKS, BATCH), 64>>>(HALF_ROWS, HALF_W);    // B2b
    nms_phase1_kernel<<<BATCH, C_NT>>>(out);                                 // C1
    iou_kept_kernel<<<dim3(HALF_W, 6, BATCH), 64>>>();                       // B2a
    nms_phase2_kernel<<<BATCH, C_NT>>>(out);                                 // C2
}

// round 17
// speedup vs baseline: 2.3451x; 1.0149x over previous
#include <cuda_runtime.h>
#include <cuda_bf16.h>
#include <cstdint>

#define IMG_N_ANC   8649      // 31*31*9
#define PRE_NMS     6000
#define POST_NMS    1500
#define IOU_THR     0.7f
#define BATCH       16
#define NW          94        // 94 u64 words cover 6016 >= 6000 cols
#define NWP         96        // padded row stride (768 B)
#define NPAD        6016
#define NBIN        2048
#define NKEY        8704
#define HALF_W      47        // phase split: words 0..46 | 47..93
#define HALF_ROWS   3008      // = HALF_W * 64

typedef unsigned long long u64;

// ---------------- device scratch (static; no allocations) ----------------
__device__ u64   g_masks[BATCH][NPAD][NWP];   // [b][row][word]
__device__ float g_y1[BATCH][NPAD];
__device__ float g_x1[BATCH][NPAD];
__device__ float g_y2[BATCH][NPAD];
__device__ float g_x2[BATCH][NPAD];
__device__ float g_ar[BATCH][NPAD];
__device__ float g_cs[BATCH][NPAD];           // ar * (0.7/1.7)
__device__ float g_sc[BATCH][NPAD];
__device__ int   g_kept[BATCH][1536];         // kept rows from phase 1
__device__ int   g_kcnt[BATCH];

// ================= Kernel A: bucket sort + decode top-6000 =================
#define A_NT          1024
#define A_OFF_RAW     0
#define A_OFF_SORT    (NKEY * 8)
#define A_OFF_HIST    (A_OFF_SORT + NKEY * 8)
#define A_OFF_START   (A_OFF_HIST + NBIN * 4)
#define A_SMEM_TOTAL  (A_OFF_START + NBIN * 4)

__global__ __launch_bounds__(A_NT, 1)
void sort_decode_kernel(const float* __restrict__ deltas,
                        const float* __restrict__ probs,
                        const float* __restrict__ anchors)
{
    extern __shared__ char smem[];
    u64* keys_raw    = (u64*)(smem + A_OFF_RAW);
    u64* keys_sorted = (u64*)(smem + A_OFF_SORT);
    unsigned int* hist  = (unsigned int*)(smem + A_OFF_HIST);
    unsigned int* start = (unsigned int*)(smem + A_OFF_START);

    const int b   = blockIdx.x;
    const int tid = threadIdx.x;
    const int nt  = A_NT;

    for (int i = tid; i < NBIN; i += nt) hist[i] = 0u;
    __syncthreads();

    const float* pb = probs + (size_t)b * IMG_N_ANC;
    for (int i = tid; i < IMG_N_ANC; i += nt) {
        float s = pb[i];
        unsigned int bits = __float_as_uint(s);
        u64 k = ((u64)bits << 32) | (u64)(0xFFFFFFFFu - (unsigned)i);
        keys_raw[i] = k;
        int bin = (int)(s * (float)NBIN);
        bin = max(0, min(NBIN - 1, bin));
        atomicAdd(&hist[bin], 1u);
    }
    __syncthreads();

    if (tid < 32) {
        const int lane = tid;
        int part = 0;
        #pragma unroll 8
        for (int q = 0; q < 64; q++) part += (int)hist[NBIN - 1 - (lane * 64 + q)];
        int inc = part;
        #pragma unroll
        for (int off = 1; off < 32; off <<= 1) {
            int v = __shfl_up_sync(0xFFFFFFFFu, inc, off);
            if (lane >= off) inc += v;
        }
        int excl = inc - part;
        for (int q = 0; q < 64; q++) {
            int v = NBIN - 1 - (lane * 64 + q);
            start[v] = (unsigned int)excl;
            excl += (int)hist[v];
        }
    }
    __syncthreads();

    for (int i = tid; i < NBIN; i += nt) hist[i] = 0u;
    __syncthreads();

    for (int i = tid; i < IMG_N_ANC; i += nt) {
        u64 k = keys_raw[i];
        float s = __uint_as_float((unsigned int)(k >> 32));
        int bin = (int)(s * (float)NBIN);
        bin = max(0, min(NBIN - 1, bin));
        unsigned int pos = start[bin] + atomicAdd(&hist[bin], 1u);
        keys_sorted[pos] = k;
    }
    __syncthreads();

    for (int v = tid; v < NBIN; v += nt) {
        int s0 = (int)start[v];
        int c  = (int)hist[v];
        if (s0 < PRE_NMS && c > 1) {
            for (int a = s0 + 1; a < s0 + c; a++) {
                u64 key = keys_sorted[a];
                int p = a - 1;
                while (p >= s0 && keys_sorted[p] < key) {
                    keys_sorted[p + 1] = keys_sorted[p];
                    p--;
                }
                keys_sorted[p + 1] = key;
            }
        }
    }
    __syncthreads();

    const float* db = deltas + (size_t)b * IMG_N_ANC * 4;
    for (int t = tid; t < PRE_NMS; t += nt) {
        u64 key = keys_sorted[t];
        unsigned int idx = 0xFFFFFFFFu - (unsigned int)(key & 0xFFFFFFFFull);
        float score = __uint_as_float((unsigned int)(key >> 32));

        float a0 = anchors[idx * 4 + 0];
        float a1 = anchors[idx * 4 + 1];
        float a2 = anchors[idx * 4 + 2];
        float a3 = anchors[idx * 4 + 3];
        float d0 = db[(size_t)idx * 4 + 0] * 0.1f;
        float d1 = db[(size_t)idx * 4 + 1] * 0.1f;
        float d2 = db[(size_t)idx * 4 + 2] * 0.2f;
        float d3 = db[(size_t)idx * 4 + 3] * 0.2f;

        float anc_h = a2 - a0;
        float anc_w = a3 - a1;
        float ctr_y = a0 + 0.5f * anc_h;
        float ctr_x = a1 + 0.5f * anc_w;
        float bh = expf(d2) * anc_h;
        float bw = expf(d3) * anc_w;
        float bcy = d0 * anc_h + ctr_y;
        float bcx = d1 * anc_w + ctr_x;
        float y1 = bcy - 0.5f * bh;
        float x1 = bcx - 0.5f * bw;
        float y2 = y1 + bh;
        float x2 = x1 + bw;

        float ar = (y2 - y1) * (x2 - x1);
        g_y1[b][t] = y1; g_x1[b][t] = x1;
        g_y2[b][t] = y2; g_x2[b][t] = x2;
        g_ar[b][t] = ar;
        g_cs[b][t] = ar * (IOU_THR / (1.0f + IOU_THR));
        g_sc[b][t] = score;
    }
}

// ===================== B core constants (proven R15) ========================
#define B_RELB   4e-6f
#define B_ABSB   2e-8f
#define B_TRI_BLOCKS 300   // sum over rb=0..11 of (47 - 4*rb)

__device__ __forceinline__ bool iou_exact_hit(float ry1, float rx1, float ry2,
                                              float rx2, float rar,
                                              float4 c4, float ca)
{
    float ih = fmaxf(fminf(ry2, c4.z) - fmaxf(ry1, c4.x), 0.0f);
    float iw = fmaxf(fminf(rx2, c4.w) - fmaxf(rx1, c4.y), 0.0f);
    float inter = __fmul_rn(ih, iw);
    float dd = __fadd_rn(__fadd_rn(__fadd_rn(rar, ca), -inter), 1e-8f);
    return __fdiv_rn(inter, dd) > IOU_THR;
}

// ============ Kernel B-tri: triangle half (rows x words of one phase) =======
__global__ __launch_bounds__(64)
void iou_tri_kernel(int row_base, int colw_base)
{
    int t = blockIdx.x;
    int rb = 0;
    while (t >= 47 - 4 * rb) { t -= 47 - 4 * rb; rb++; }
    const int cb = colw_base + 4 * rb + t;
    const int b   = blockIdx.y;
    const int tid = threadIdx.x;

    __shared__ float4 cbox[64];
    __shared__ float  cncs[64];
    __shared__ float  care[64];
    __shared__ float  s_cnmin[2];

    const int j0 = cb * 64;
    float myncs;
    {
        int j = j0 + tid;
        if (j < PRE_NMS) {
            cbox[tid] = make_float4(g_y1[b][j], g_x1[b][j], g_y2[b][j], g_x2[b][j]);
            myncs = -g_cs[b][j];
            care[tid] = g_ar[b][j];
        } else {
            cbox[tid] = make_float4(0.f, 0.f, 0.f, 0.f);
            myncs = 0.f;
            care[tid] = 0.f;
        }
        cncs[tid] = myncs;
    }
    {
        float v = myncs;
        #pragma unroll
        for (int off = 16; off > 0; off >>= 1)
            v = fminf(v, __shfl_xor_sync(0xFFFFFFFFu, v, off));
        if ((tid & 31) == 0) s_cnmin[tid >> 5] = v;
    }
    __syncthreads();
    const float cnmin = fminf(s_cnmin[0], s_cnmin[1]);

    float ry1[4], rx1[4], ry2[4], rx2[4], rncs[4], rar[4];
    #pragma unroll
    for (int r = 0; r < 4; r++) {
        int i = row_base + rb * 256 + r * 64 + tid;
        int ii = (i < PRE_NMS) ? i : 0;
        ry1[r] = g_y1[b][ii]; rx1[r] = g_x1[b][ii];
        ry2[r] = g_y2[b][ii]; rx2[r] = g_x2[b][ii];
        rncs[r] = -g_cs[b][ii]; rar[r] = g_ar[b][ii];
    }

    unsigned int ahi[4] = {0,0,0,0}, alo[4] = {0,0,0,0};
    float dmin[4] = {1e30f, 1e30f, 1e30f, 1e30f};

    #pragma unroll 8
    for (int j = 63; j >= 32; j--) {
        float4 c4 = cbox[j];
        float ncc = cncs[j];
        #pragma unroll
        for (int r = 0; r < 4; r++) {
            float ih = fmaxf(fminf(ry2[r], c4.z) - fmaxf(ry1[r], c4.x), 0.0f);
            float iw = fminf(rx2[r], c4.w) - fmaxf(rx1[r], c4.y);
            float nss  = rncs[r] + ncc;
            float diff = fmaf(ih, iw, nss);
            dmin[r] = fminf(dmin[r], fabsf(diff));
            ahi[r] = __funnelshift_l(__float_as_uint(diff), ahi[r], 1);
        }
    }
    #pragma unroll 8
    for (int j = 31; j >= 0; j--) {
        float4 c4 = cbox[j];
        float ncc = cncs[j];
        #pragma unroll
        for (int r = 0; r < 4; r++) {
            float ih = fmaxf(fminf(ry2[r], c4.z) - fmaxf(ry1[r], c4.x), 0.0f);
            float iw = fminf(rx2[r], c4.w) - fmaxf(rx1[r], c4.y);
            float nss  = rncs[r] + ncc;
            float diff = fmaf(ih, iw, nss);
            dmin[r] = fminf(dmin[r], fabsf(diff));
            alo[r] = __funnelshift_l(__float_as_uint(diff), alo[r], 1);
        }
    }

    unsigned int bhi[4], blo[4];
    #pragma unroll
    for (int r = 0; r < 4; r++) { bhi[r] = ~ahi[r]; blo[r] = ~alo[r]; }

    #pragma unroll
    for (int r = 0; r < 4; r++) {
        float thr = fmaf(B_RELB, -(rncs[r] + cnmin), B_ABSB);
        if (dmin[r] <= thr) {
            for (int j = 0; j < 64; j++) {
                float4 c4 = cbox[j];
                float ncc = cncs[j];
                float ih = fmaxf(fminf(ry2[r], c4.z) - fmaxf(ry1[r], c4.x), 0.0f);
                float iw = fminf(rx2[r], c4.w) - fmaxf(rx1[r], c4.y);
                float nss  = rncs[r] + ncc;
                float diff = fmaf(ih, iw, nss);
                float nthr = fmaf(B_RELB, nss, -B_ABSB);
                if (fabsf(diff) + nthr <= 0.0f) {
                    bool hit = iou_exact_hit(ry1[r], rx1[r], ry2[r], rx2[r],
                                             rar[r], c4, care[j]);
                    if (j < 32)
                        blo[r] = hit ? (blo[r] | (1u << j)) : (blo[r] & ~(1u << j));
                    else
                        bhi[r] = hit ? (bhi[r] | (1u << (j - 32)))
                                     : (bhi[r] & ~(1u << (j - 32)));
                }
            }
        }
    }

    #pragma unroll
    for (int r = 0; r < 4; r++) {
        int i = row_base + rb * 256 + r * 64 + tid;
        if (i < PRE_NMS && cb >= (i >> 6)) {
            u64 bits = ((u64)bhi[r] << 32) | (u64)blo[r];
            int dlt = i - j0;
            u64 m = (dlt < 0) ? ~0ull : ((dlt >= 63) ? 0ull : (~0ull << (dlt + 1)));
            g_masks[b][i][cb] = bits & m;
        }
    }
}

// ====== Kernel B2a: kept phase-1 rows x phase-2 words =======================
__global__ __launch_bounds__(64)
void iou_kept_kernel()
{
    const int cb  = HALF_W + blockIdx.x;
    const int b   = blockIdx.z;
    const int tid = threadIdx.x;
    const int kcnt = g_kcnt[b];
    if (blockIdx.y * 256 >= kcnt) return;

    __shared__ float4 cbox[64];
    __shared__ float  cncs[64];
    __shared__ float  care[64];
    __shared__ float  s_cnmin[2];

    const int j0 = cb * 64;
    float myncs;
    {
        int j = j0 + tid;
        if (j < PRE_NMS) {
            cbox[tid] = make_float4(g_y1[b][j], g_x1[b][j], g_y2[b][j], g_x2[b][j]);
            myncs = -g_cs[b][j];
            care[tid] = g_ar[b][j];
        } else {
            cbox[tid] = make_float4(0.f, 0.f, 0.f, 0.f);
            myncs = 0.f;
            care[tid] = 0.f;
        }
        cncs[tid] = myncs;
    }
    {
        float v = myncs;
        #pragma unroll
        for (int off = 16; off > 0; off >>= 1)
            v = fminf(v, __shfl_xor_sync(0xFFFFFFFFu, v, off));
        if ((tid & 31) == 0) s_cnmin[tid >> 5] = v;
    }
    __syncthreads();
    const float cnmin = fminf(s_cnmin[0], s_cnmin[1]);

    float ry1[4], rx1[4], ry2[4], rx2[4], rncs[4], rar[4];
    int   ri[4];
    bool  act[4];
    #pragma unroll
    for (int r = 0; r < 4; r++) {
        int m = blockIdx.y * 256 + r * 64 + tid;
        act[r] = (m < kcnt);
        int row = act[r] ? g_kept[b][m] : 0;
        ri[r] = row;
        ry1[r] = g_y1[b][row]; rx1[r] = g_x1[b][row];
        ry2[r] = g_y2[b][row]; rx2[r] = g_x2[b][row];
        rncs[r] = -g_cs[b][row]; rar[r] = g_ar[b][row];
    }

    unsigned int ahi[4] = {0,0,0,0}, alo[4] = {0,0,0,0};
    float dmin[4] = {1e30f, 1e30f, 1e30f, 1e30f};

    #pragma unroll 8
    for (int j = 63; j >= 32; j--) {
        float4 c4 = cbox[j];
        float ncc = cncs[j];
        #pragma unroll
        for (int r = 0; r < 4; r++) {
            float ih = fmaxf(fminf(ry2[r], c4.z) - fmaxf(ry1[r], c4.x), 0.0f);
            float iw = fminf(rx2[r], c4.w) - fmaxf(rx1[r], c4.y);
            float nss  = rncs[r] + ncc;
            float diff = fmaf(ih, iw, nss);
            dmin[r] = fminf(dmin[r], fabsf(diff));
            ahi[r] = __funnelshift_l(__float_as_uint(diff), ahi[r], 1);
        }
    }
    #pragma unroll 8
    for (int j = 31; j >= 0; j--) {
        float4 c4 = cbox[j];
        float ncc = cncs[j];
        #pragma unroll
        for (int r = 0; r < 4; r++) {
            float ih = fmaxf(fminf(ry2[r], c4.z) - fmaxf(ry1[r], c4.x), 0.0f);
            float iw = fminf(rx2[r], c4.w) - fmaxf(rx1[r], c4.y);
            float nss  = rncs[r] + ncc;
            float diff = fmaf(ih, iw, nss);
            dmin[r] = fminf(dmin[r], fabsf(diff));
            alo[r] = __funnelshift_l(__float_as_uint(diff), alo[r], 1);
        }
    }

    unsigned int bhi[4], blo[4];
    #pragma unroll
    for (int r = 0; r < 4; r++) { bhi[r] = ~ahi[r]; blo[r] = ~alo[r]; }

    #pragma unroll
    for (int r = 0; r < 4; r++) {
        float thr = fmaf(B_RELB, -(rncs[r] + cnmin), B_ABSB);
        if (act[r] && dmin[r] <= thr) {
            for (int j = 0; j < 64; j++) {
                float4 c4 = cbox[j];
                float ncc = cncs[j];
                float ih = fmaxf(fminf(ry2[r], c4.z) - fmaxf(ry1[r], c4.x), 0.0f);
                float iw = fminf(rx2[r], c4.w) - fmaxf(rx1[r], c4.y);
                float nss  = rncs[r] + ncc;
                float diff = fmaf(ih, iw, nss);
                float nthr = fmaf(B_RELB, nss, -B_ABSB);
                if (fabsf(diff) + nthr <= 0.0f) {
                    bool hit = iou_exact_hit(ry1[r], rx1[r], ry2[r], rx2[r],
                                             rar[r], c4, care[j]);
                    if (j < 32)
                        blo[r] = hit ? (blo[r] | (1u << j)) : (blo[r] & ~(1u << j));
                    else
                        bhi[r] = hit ? (bhi[r] | (1u << (j - 32)))
                                     : (bhi[r] & ~(1u << (j - 32)));
                }
            }
        }
    }

    #pragma unroll
    for (int r = 0; r < 4; r++) {
        if (act[r]) {
            u64 bits = ((u64)bhi[r] << 32) | (u64)blo[r];
            g_masks[b][ri[r]][cb] = bits;
        }
    }
}

// ================= Kernel C1: chunks 0..46, record kept rows ================
// R16 structure with two C-only fixes:
//  - def loads truly predicated (if-guard), DEFN 8; overflow keeps sync OR
//  - publisher spec: unconditional 64-row coverage (immediate addresses,
//    no serial alive-bit chain); selected by kept bits at consume
#define C_NT 512
#define DEFN 8

__global__ __launch_bounds__(C_NT, 1)
void nms_phase1_kernel(float* __restrict__ out)
{
    const int b   = blockIdx.x;
    const int tid = threadIdx.x;

    __shared__ u64 s_diag[64];
    __shared__ u64 s_pub[4];
    __shared__ u64 s_keptmask;
    __shared__ int s_rows[64];
    __shared__ int s_nk;

    float* ob = out + (size_t)b * POST_NMS * 4;
    float* os = out + (size_t)BATCH * POST_NMS * 4 + (size_t)b * POST_NMS;

    for (int t = tid; t < POST_NMS * 4; t += C_NT) ob[t] = 0.0f;
    for (int t = tid; t < POST_NMS; t += C_NT)     os[t] = 0.0f;

    const int w   = tid >> 2;
    const int sub = tid & 3;
    u64 rem = 0ull;
    u64 def[DEFN];
    #pragma unroll
    for (int q = 0; q < DEFN; q++) def[q] = 0ull;

    if (tid >= 448) s_diag[tid - 448] = g_masks[b][tid - 448][0];
    if (tid < 4) s_pub[tid] = 0ull;
    __syncthreads();

    int cnt = 0;
    for (int c = 0; c < HALF_W; c++) {
        u64 remc = s_pub[0] | s_pub[1] | s_pub[2] | s_pub[3];
        u64 alive = ~remc;      // lim always 64 for c < 47

        if (tid < 376 && w > c && w < HALF_W) {
            #pragma unroll
            for (int q = 0; q < DEFN; q++) rem |= def[q];
            #pragma unroll
            for (int q = 0; q < DEFN; q++) def[q] = 0ull;
        }

        // publisher spec: all 64 chunk rows, immediate addresses
        const bool is_pub = (tid < 376) && (w == c + 1) && (c + 1 < HALF_W);
        u64 spec[16];
        if (is_pub) {
            #pragma unroll
            for (int q = 0; q < 16; q++)
                spec[q] = g_masks[b][c * 64 + (q * 4 + sub)][w];
        }

        if (tid == 0) {
            u64 av = alive;
            u64 kept = 0ull;
            int nk = 0, cc = cnt;
            while (av && cc < POST_NMS) {
                int i = __ffsll((long long)av) - 1;
                s_rows[nk++] = c * 64 + i;
                kept |= (1ull << i);
                cc++;
                av &= ~(s_diag[i] | (1ull << i));
            }
            s_nk = nk;
            s_keptmask = kept;
        }
        __syncthreads();
        const int nk = s_nk;
        const u64 kept = s_keptmask;

        if (tid < nk) {
            int r    = s_rows[tid];
            int rank = cnt + tid;
            ob[rank * 4 + 0] = fminf(fmaxf(g_y1[b][r], 0.0f), 1.0f);
            ob[rank * 4 + 1] = fminf(fmaxf(g_x1[b][r], 0.0f), 1.0f);
            ob[rank * 4 + 2] = fminf(fmaxf(g_y2[b][r], 0.0f), 1.0f);
            ob[rank * 4 + 3] = fminf(fmaxf(g_x2[b][r], 0.0f), 1.0f);
            os[rank] = g_sc[b][r];
            g_kept[b][rank] = r;
        }

        if (tid < 376 && w > c + 1 && w < HALF_W) {
            #pragma unroll
            for (int q = 0; q < DEFN; q++) {
                int m = sub + q * 4;
                if (m < nk) def[q] = g_masks[b][s_rows[m]][w];   // @P LDG
            }
            for (int m = sub + DEFN * 4; m < nk; m += 4)
                rem |= g_masks[b][s_rows[m]][w];
        }

        if (is_pub) {
            #pragma unroll
            for (int q = 0; q < 16; q++) {
                if ((kept >> (q * 4 + sub)) & 1ull) rem |= spec[q];
            }
            s_pub[sub] = rem;
        }

        if (c + 1 < HALF_W && tid >= 448) {
            int row = (c + 1) * 64 + (tid - 448);
            s_diag[tid - 448] = g_masks[b][row][c + 1];
        }

        cnt += nk;
        __syncthreads();
        if (cnt >= POST_NMS) break;
    }

    if (tid == 0) g_kcnt[b] = cnt;
}

// ================= Kernel C2: prologue OR + chunks 47..93 ===================
__global__ __launch_bounds__(C_NT, 1)
void nms_phase2_kernel(float* __restrict__ out)
{
    const int b   = blockIdx.x;
    const int tid = threadIdx.x;

    __shared__ u64 s_diag[64];
    __shared__ u64 s_pub[4];
    __shared__ u64 s_keptmask;
    __shared__ int s_rows[64];
    __shared__ int s_nk;

    float* ob = out + (size_t)b * POST_NMS * 4;
    float* os = out + (size_t)BATCH * POST_NMS * 4 + (size_t)b * POST_NMS;

    const int w   = tid >> 2;
    const int sub = tid & 3;
    const int kcnt = g_kcnt[b];
    u64 rem = 0ull;
    u64 def[DEFN];
    #pragma unroll
    for (int q = 0; q < DEFN; q++) def[q] = 0ull;

    // prologue: fold phase-1 kept rows' suppression into owner words >= 47
    if (tid < 376 && w >= HALF_W) {
        for (int m = sub; m < kcnt; m += 4)
            rem |= g_masks[b][g_kept[b][m]][w];
    }
    if (tid < 376 && w == HALF_W) s_pub[sub] = rem;
    if (tid >= 448) s_diag[tid - 448] = g_masks[b][HALF_W * 64 + (tid - 448)][HALF_W];
    __syncthreads();

    int cnt = kcnt;
    for (int c = HALF_W; c < NW; c++) {
        u64 remc = s_pub[0] | s_pub[1] | s_pub[2] | s_pub[3];
        int lim = PRE_NMS - c * 64;
        u64 alive = ~remc;
        if (lim < 64) alive &= ((1ull << lim) - 1ull);

        if (tid < 376 && w > c) {
            #pragma unroll
            for (int q = 0; q < DEFN; q++) rem |= def[q];
            #pragma unroll
            for (int q = 0; q < DEFN; q++) def[q] = 0ull;
        }

        // publisher spec: all 64 chunk rows, immediate addresses
        const bool is_pub = (tid < 376) && (w == c + 1);
        u64 spec[16];
        if (is_pub) {
            #pragma unroll
            for (int q = 0; q < 16; q++)
                spec[q] = g_masks[b][c * 64 + (q * 4 + sub)][w];
        }

        if (tid == 0) {
            u64 av = alive;
            u64 kept = 0ull;
            int nk = 0, cc = cnt;
            while (av && cc < POST_NMS) {
                int i = __ffsll((long long)av) - 1;
                s_rows[nk++] = c * 64 + i;
                kept |= (1ull << i);
                cc++;
                av &= ~(s_diag[i] | (1ull << i));
            }
            s_nk = nk;
            s_keptmask = kept;
        }
        __syncthreads();
        const int nk = s_nk;
        const u64 kept = s_keptmask;

        if (tid < nk) {
            int r    = s_rows[tid];
            int rank = cnt + tid;
            ob[rank * 4 + 0] = fminf(fmaxf(g_y1[b][r], 0.0f), 1.0f);
            ob[rank * 4 + 1] = fminf(fmaxf(g_x1[b][r], 0.0f), 1.0f);
            ob[rank * 4 + 2] = fminf(fmaxf(g_y2[b][r], 0.0f), 1.0f);
            ob[rank * 4 + 3] = fminf(fmaxf(g_x2[b][r], 0.0f), 1.0f);
            os[rank] = g_sc[b][r];
        }

        if (tid < 376 && w > c + 1) {
            #pragma unroll
            for (int q = 0; q < DEFN; q++) {
                int m = sub + q * 4;
                if (m < nk) def[q] = g_masks[b][s_rows[m]][w];   // @P LDG
            }
            for (int m = sub + DEFN * 4; m < nk; m += 4)
                rem |= g_masks[b][s_rows[m]][w];
        }

        if (is_pub) {
            #pragma unroll
            for (int q = 0; q < 16; q++) {
                if ((kept >> (q * 4 + sub)) & 1ull) rem |= spec[q];
            }
            s_pub[sub] = rem;
        }

        if (c + 1 < NW && tid >= 448) {
            int row = (c + 1) * 64 + (tid - 448);
            s_diag[tid - 448] = (row < PRE_NMS) ? g_masks[b][row][c + 1] : 0ull;
        }

        cnt += nk;
        __syncthreads();
        if (cnt >= POST_NMS) break;
    }
}

// ============================== launch =====================================
extern "C" void kernel_launch(void* const* d_in, const int* in_sizes, int n_in,
                              void* d_out, int out_size) {
    const float* deltas  = (const float*)d_in[0];
    const float* probs   = (const float*)d_in[1];
    const float* anchors = (const float*)d_in[2];
    float* out = (float*)d_out;

    cudaFuncSetAttribute(sort_decode_kernel,
                         cudaFuncAttributeMaxDynamicSharedMemorySize, A_SMEM_TOTAL);

    sort_decode_kernel<<<BATCH, A_NT, A_SMEM_TOTAL>>>(deltas, probs, anchors);
    iou_tri_kernel<<<dim3(B_TRI_BLOCKS, BATCH), 64>>>(0, 0);                 // B1
    iou_tri_kernel<<<dim3(B_TRI_BLOCKS, BATCH), 64>>>(HALF_ROWS, HALF_W);    // B2b
    nms_phase1_kernel<<<BATCH, C_NT>>>(out);                                 // C1
    iou_kept_kernel<<<dim3(HALF_W, 6, BATCH), 64>>>();                       // B2a
    nms_phase2_kernel<<<BATCH, C_NT>>>(out);                                 // C2
}